// round 1
// baseline (speedup 1.0000x reference)
#include <cuda_runtime.h>
#include <cuda_bf16.h>
#include <math.h>

// ---------------------------------------------------------------------------
// Problem constants
//   B=4, T1=2048, TKV*N=J=512, DIM=1024, DL=1024, H=8, DH=64, INNER=512, DFF=4096
// ---------------------------------------------------------------------------
#define B_     4
#define T1_    2048
#define JT_    512
#define DIM_   1024
#define INNER_ 512
#define DFF_   4096
#define H_     8
#define DH_    64

// ---------------------------------------------------------------------------
// Scratch (device globals; no allocation allowed)
// ---------------------------------------------------------------------------
__device__ float g_lnbuf[(size_t)B_*T1_*DIM_];   // LN(qo) then LN(x)   (33.5 MB)
__device__ float g_q   [(size_t)B_*T1_*INNER_];  // q projection        (16.8 MB)
__device__ float g_kv  [(size_t)B_*JT_*2*INNER_];// k|v projection      ( 8.4 MB)
__device__ float g_ao  [(size_t)B_*T1_*INNER_];  // attention output    (16.8 MB)
__device__ float g_x   [(size_t)B_*T1_*DIM_];    // attn residual       (33.5 MB)
__device__ float g_h   [(size_t)B_*T1_*DFF_];    // gelu(ff1)           ( 134 MB)
__device__ int   g_mask_mode;                    // 0=uint8, 1=int32, 2=float32

// ---------------------------------------------------------------------------
// Mask dtype detection: bool tensors may arrive as uint8, int32, or float32.
// Inspect raw words of attn_mask:
//   float32 bools -> words are 0x0 or 0x3F800000
//   int32 bools   -> words are 0x0 or 0x1
//   uint8 bools   -> words have mixed-byte patterns (w.h.p. over 2048 words)
// ---------------------------------------------------------------------------
__global__ void detect_mask_kernel(const unsigned int* __restrict__ w, int nwords)
{
    __shared__ int f_u8, f_f32;
    if (threadIdx.x == 0) { f_u8 = 0; f_f32 = 0; }
    __syncthreads();
    int u8 = 0, f32 = 0;
    for (int i = threadIdx.x; i < nwords; i += blockDim.x) {
        unsigned int x = w[i];
        if (x == 0x3F800000u)            f32 = 1;
        else if (x != 0u && x != 1u)     u8  = 1;
    }
    if (u8)  atomicOr(&f_u8, 1);
    if (f32) atomicOr(&f_f32, 1);
    __syncthreads();
    if (threadIdx.x == 0)
        g_mask_mode = f_u8 ? 0 : (f_f32 ? 2 : 1);
}

__device__ __forceinline__ bool read_mask(const void* p, size_t i, int mode)
{
    if (mode == 1) return ((const int*)p)[i] != 0;
    if (mode == 2) return ((const float*)p)[i] != 0.0f;
    return ((const unsigned char*)p)[i] != 0;
}

// ---------------------------------------------------------------------------
// LayerNorm over last dim (1024). One block per row, 256 threads.
// var = E[x^2] - mu^2 (population, matches jnp.var), eps inside sqrt.
// ---------------------------------------------------------------------------
__global__ __launch_bounds__(256) void ln_kernel(
    const float* __restrict__ x, const float* __restrict__ gw,
    const float* __restrict__ bw, float* __restrict__ y)
{
    const int row = blockIdx.x;
    const float* xr = x + (size_t)row * DIM_;
    float v[4];
    float s = 0.f, s2 = 0.f;
    #pragma unroll
    for (int k = 0; k < 4; k++) {
        v[k] = xr[threadIdx.x + k * 256];
        s += v[k]; s2 += v[k] * v[k];
    }
    #pragma unroll
    for (int o = 16; o; o >>= 1) {
        s  += __shfl_xor_sync(0xffffffffu, s,  o);
        s2 += __shfl_xor_sync(0xffffffffu, s2, o);
    }
    __shared__ float sh[2][8];
    const int warp = threadIdx.x >> 5, lane = threadIdx.x & 31;
    if (lane == 0) { sh[0][warp] = s; sh[1][warp] = s2; }
    __syncthreads();
    if (threadIdx.x == 0) {
        float S = 0.f, S2 = 0.f;
        #pragma unroll
        for (int w = 0; w < 8; w++) { S += sh[0][w]; S2 += sh[1][w]; }
        const float mu  = S  * (1.0f / DIM_);
        const float var = S2 * (1.0f / DIM_) - mu * mu;
        sh[0][0] = mu;
        sh[1][0] = rsqrtf(var + 1e-5f);
    }
    __syncthreads();
    const float mu = sh[0][0], inv = sh[1][0];
    float* yr = y + (size_t)row * DIM_;
    #pragma unroll
    for (int k = 0; k < 4; k++) {
        const int c = threadIdx.x + k * 256;
        yr[c] = (v[k] - mu) * inv * gw[c] + bw[c];
    }
}

// ---------------------------------------------------------------------------
// SGEMM: C[M,N] = epilogue(A[M,K] @ B[K,N])
// 128x128 block tile, BK=8, 256 threads, 8x8 per-thread register tile.
// M % 128 == 0, N % 128 == 0, K % 8 == 0 for all call sites.
// EPI: 0 = none, 1 = exact GELU, 2 = v*tanh(*gate) + res[r,c]
// ---------------------------------------------------------------------------
template <int EPI>
__global__ __launch_bounds__(256) void sgemm_kernel(
    const float* __restrict__ A, const float* __restrict__ Bm,
    float* __restrict__ C, int M, int N, int K,
    const float* __restrict__ gate, const float* __restrict__ res)
{
    __shared__ float As[8][128];
    __shared__ float Bs[8][128];
    const int tid = threadIdx.x;
    const int tx = tid & 15, ty = tid >> 4;
    const int row0 = blockIdx.y << 7, col0 = blockIdx.x << 7;

    const int a_r = tid >> 1,  a_c = (tid & 1) << 2;   // 128 rows x 8 cols (float4)
    const int b_r = tid >> 5,  b_c = (tid & 31) << 2;  //   8 rows x 128 cols (float4)

    const float* Ap = A  + (size_t)(row0 + a_r) * K + a_c;
    const float* Bp = Bm + (size_t)b_r * N + col0 + b_c;

    float acc[8][8];
    #pragma unroll
    for (int i = 0; i < 8; i++)
        #pragma unroll
        for (int j = 0; j < 8; j++) acc[i][j] = 0.f;

    for (int k0 = 0; k0 < K; k0 += 8) {
        const float4 av = *reinterpret_cast<const float4*>(Ap + k0);
        As[a_c + 0][a_r] = av.x; As[a_c + 1][a_r] = av.y;
        As[a_c + 2][a_r] = av.z; As[a_c + 3][a_r] = av.w;
        *reinterpret_cast<float4*>(&Bs[b_r][b_c]) =
            *reinterpret_cast<const float4*>(Bp + (size_t)k0 * N);
        __syncthreads();
        #pragma unroll
        for (int kk = 0; kk < 8; kk++) {
            const float4 a0 = *reinterpret_cast<const float4*>(&As[kk][ty << 3]);
            const float4 a1 = *reinterpret_cast<const float4*>(&As[kk][(ty << 3) + 4]);
            const float4 b0 = *reinterpret_cast<const float4*>(&Bs[kk][tx << 3]);
            const float4 b1 = *reinterpret_cast<const float4*>(&Bs[kk][(tx << 3) + 4]);
            const float a[8]  = {a0.x, a0.y, a0.z, a0.w, a1.x, a1.y, a1.z, a1.w};
            const float bb[8] = {b0.x, b0.y, b0.z, b0.w, b1.x, b1.y, b1.z, b1.w};
            #pragma unroll
            for (int i = 0; i < 8; i++)
                #pragma unroll
                for (int j = 0; j < 8; j++)
                    acc[i][j] = fmaf(a[i], bb[j], acc[i][j]);
        }
        __syncthreads();
    }

    float g = 0.f;
    if (EPI == 2) g = tanhf(gate[0]);
    #pragma unroll
    for (int i = 0; i < 8; i++) {
        const size_t rr = (size_t)(row0 + (ty << 3) + i);
        #pragma unroll
        for (int j = 0; j < 8; j++) {
            const size_t cc = (size_t)(col0 + (tx << 3) + j);
            float v = acc[i][j];
            if (EPI == 1) v = 0.5f * v * (1.0f + erff(v * 0.70710678118654752f));
            if (EPI == 2) v = v * g + res[rr * N + cc];
            C[rr * N + cc] = v;
        }
    }
}

// ---------------------------------------------------------------------------
// Fused masked cross-attention.
// grid = (T1/64, H, B); 256 threads; thread = (row r in 0..63, sub in 0..3).
// Each thread runs an online softmax over its own 32-key slice (4 tiles of
// 128 keys, jl = jj*4+sub), keeps a full 64-dim partial accumulator, then the
// 4 sub-lanes of a row merge via shfl. Fully-masked rows emit exact zeros
// (matches row_has_key semantics). Output includes q_mask multiply.
// ---------------------------------------------------------------------------
#define ATTN_PAD 68
#define ATTN_SMEM ((64 + 128 + 128) * ATTN_PAD * 4 + 128)

__global__ __launch_bounds__(256) void attn_kernel(
    const float* __restrict__ Q,    // (B*T1, INNER) unscaled
    const float* __restrict__ KV,   // (B*J, 2*INNER): k cols [0,512), v cols [512,1024)
    const void*  __restrict__ amask,// (B, T1, J) bool
    const void*  __restrict__ kvmask,// (B, J) bool
    const float* __restrict__ qmask,// (B, T1) f32
    float* __restrict__ AO)         // (B*T1, INNER)
{
    extern __shared__ float sm[];
    float* Qs = sm;                       // 64  x 68
    float* Ks = sm + 64 * ATTN_PAD;       // 128 x 68
    float* Vs = Ks + 128 * ATTN_PAD;      // 128 x 68
    unsigned char* kvm = (unsigned char*)(Vs + 128 * ATTN_PAD);

    const int i0 = blockIdx.x * 64;
    const int h  = blockIdx.y;
    const int b  = blockIdx.z;
    const int tid = threadIdx.x;
    const int r = tid >> 2, sub = tid & 3;
    const int mode = g_mask_mode;

    // Q tile, pre-scaled by DH^-0.5 = 0.125
    for (int t = tid; t < 64 * 16; t += 256) {
        const int rr = t >> 4, c4 = (t & 15) << 2;
        const float4 qv = *reinterpret_cast<const float4*>(
            Q + ((size_t)(b * T1_ + i0 + rr)) * INNER_ + h * DH_ + c4);
        float* dst = Qs + rr * ATTN_PAD + c4;
        dst[0] = qv.x * 0.125f; dst[1] = qv.y * 0.125f;
        dst[2] = qv.z * 0.125f; dst[3] = qv.w * 0.125f;
    }

    float m = -1e38f, l = 0.f;
    float acc[64];
    #pragma unroll
    for (int d = 0; d < 64; d++) acc[d] = 0.f;

    const size_t am_base = ((size_t)(b * T1_ + i0 + r)) * JT_;

    for (int kt = 0; kt < 4; kt++) {
        __syncthreads();   // previous tile fully consumed before overwrite
        for (int t = tid; t < 128 * 16; t += 256) {
            const int rr = t >> 4, c4 = (t & 15) << 2;
            const float* kp = KV + ((size_t)(b * JT_ + kt * 128 + rr)) * (2 * INNER_)
                                 + h * DH_ + c4;
            const float4 k4 = *reinterpret_cast<const float4*>(kp);
            const float4 v4 = *reinterpret_cast<const float4*>(kp + INNER_);
            float* kd = Ks + rr * ATTN_PAD + c4;
            kd[0] = k4.x; kd[1] = k4.y; kd[2] = k4.z; kd[3] = k4.w;
            float* vd = Vs + rr * ATTN_PAD + c4;
            vd[0] = v4.x; vd[1] = v4.y; vd[2] = v4.z; vd[3] = v4.w;
        }
        if (tid < 128)
            kvm[tid] = read_mask(kvmask, (size_t)b * JT_ + kt * 128 + tid, mode) ? 1 : 0;
        __syncthreads();

        float s[32];
        unsigned keep = 0u;
        float tmax = -1e38f;
        #pragma unroll
        for (int jj = 0; jj < 32; jj++) {
            const int jl = (jj << 2) + sub;
            s[jj] = 0.f;
            if (kvm[jl] && read_mask(amask, am_base + kt * 128 + jl, mode)) {
                float sv = 0.f;
                const float* qp = Qs + r * ATTN_PAD;
                const float* kp = Ks + jl * ATTN_PAD;
                #pragma unroll
                for (int d = 0; d < 64; d++) sv = fmaf(qp[d], kp[d], sv);
                s[jj] = sv;
                keep |= (1u << jj);
                tmax = fmaxf(tmax, sv);
            }
        }
        if (!keep) continue;   // next stmt executed by all threads is the top sync

        const float mn = fmaxf(m, tmax);
        const float alpha = (m > -1e37f) ? __expf(m - mn) : 0.f;
        l *= alpha;
        #pragma unroll
        for (int d = 0; d < 64; d++) acc[d] *= alpha;
        #pragma unroll
        for (int jj = 0; jj < 32; jj++) {
            if (!((keep >> jj) & 1u)) continue;
            const float p = __expf(s[jj] - mn);
            l += p;
            const float* vp = Vs + ((jj << 2) + sub) * ATTN_PAD;
            #pragma unroll
            for (int d = 0; d < 64; d++) acc[d] = fmaf(p, vp[d], acc[d]);
        }
        m = mn;
    }

    // merge the 4 sub-lanes of each row (contiguous lanes: xor 1, 2)
    float mAll = m;
    mAll = fmaxf(mAll, __shfl_xor_sync(0xffffffffu, mAll, 1));
    mAll = fmaxf(mAll, __shfl_xor_sync(0xffffffffu, mAll, 2));
    const float alpha = (m > -1e37f) ? __expf(m - mAll) : 0.f;
    float lw = l * alpha;
    lw += __shfl_xor_sync(0xffffffffu, lw, 1);
    lw += __shfl_xor_sync(0xffffffffu, lw, 2);
    const float scale = (lw > 0.f) ? qmask[b * T1_ + i0 + r] / lw : 0.f;

    float* dst = AO + ((size_t)(b * T1_ + i0 + r)) * INNER_ + h * DH_;
    #pragma unroll
    for (int d = 0; d < 64; d++) {
        float a = acc[d] * alpha;
        a += __shfl_xor_sync(0xffffffffu, a, 1);
        a += __shfl_xor_sync(0xffffffffu, a, 2);
        if ((d >> 4) == sub) dst[d] = a * scale;
    }
}

// ---------------------------------------------------------------------------
// kernel_launch
// ---------------------------------------------------------------------------
extern "C" void kernel_launch(void* const* d_in, const int* in_sizes, int n_in,
                              void* d_out, int out_size)
{
    const float* qo        = (const float*)d_in[0];
    const float* kvo       = (const float*)d_in[1];
    const void*  amask     = d_in[2];
    const float* qmask     = (const float*)d_in[3];
    const void*  kvmask    = d_in[4];
    const float* ln_g      = (const float*)d_in[5];
    const float* ln_b      = (const float*)d_in[6];
    const float* Wq        = (const float*)d_in[7];
    const float* Wkv       = (const float*)d_in[8];
    const float* Wout      = (const float*)d_in[9];
    const float* attn_gate = (const float*)d_in[10];
    const float* ff_ln_g   = (const float*)d_in[11];
    const float* ff_ln_b   = (const float*)d_in[12];
    const float* W1        = (const float*)d_in[13];
    const float* W2        = (const float*)d_in[14];
    const float* ff_gate   = (const float*)d_in[15];
    float* out = (float*)d_out;

    float *lnbuf, *qb, *kvb, *aob, *xb, *hb;
    cudaGetSymbolAddress((void**)&lnbuf, g_lnbuf);
    cudaGetSymbolAddress((void**)&qb,    g_q);
    cudaGetSymbolAddress((void**)&kvb,   g_kv);
    cudaGetSymbolAddress((void**)&aob,   g_ao);
    cudaGetSymbolAddress((void**)&xb,    g_x);
    cudaGetSymbolAddress((void**)&hb,    g_h);

    // 0) classify bool-mask storage dtype (deterministic each call)
    detect_mask_kernel<<<1, 256>>>((const unsigned int*)amask, 2048);

    const int ROWS = B_ * T1_;   // 8192

    // 1) LN(qo)
    ln_kernel<<<ROWS, 256>>>(qo, ln_g, ln_b, lnbuf);
    // 2) q = LN(qo) @ Wq        (8192 x 512 x 1024)
    sgemm_kernel<0><<<dim3(INNER_ / 128, ROWS / 128), 256>>>(
        lnbuf, Wq, qb, ROWS, INNER_, DIM_, nullptr, nullptr);
    // 3) kv = kvo_flat @ Wkv    (2048 x 1024 x 1024)
    sgemm_kernel<0><<<dim3((2 * INNER_) / 128, (B_ * JT_) / 128), 256>>>(
        kvo, Wkv, kvb, B_ * JT_, 2 * INNER_, DIM_, nullptr, nullptr);
    // 4) fused masked attention -> g_ao
    cudaFuncSetAttribute(attn_kernel, cudaFuncAttributeMaxDynamicSharedMemorySize,
                         ATTN_SMEM);
    attn_kernel<<<dim3(T1_ / 64, H_, B_), 256, ATTN_SMEM>>>(
        qb, kvb, amask, kvmask, qmask, aob);
    // 5) x = (ao @ Wout) * tanh(attn_gate) + qo   (8192 x 1024 x 512)
    sgemm_kernel<2><<<dim3(DIM_ / 128, ROWS / 128), 256>>>(
        aob, Wout, xb, ROWS, DIM_, INNER_, attn_gate, qo);
    // 6) LN(x)
    ln_kernel<<<ROWS, 256>>>(xb, ff_ln_g, ff_ln_b, lnbuf);
    // 7) h = gelu(LN(x) @ W1)   (8192 x 4096 x 1024)
    sgemm_kernel<1><<<dim3(DFF_ / 128, ROWS / 128), 256>>>(
        lnbuf, W1, hb, ROWS, DFF_, DIM_, nullptr, nullptr);
    // 8) out = (h @ W2) * tanh(ff_gate) + x   (8192 x 1024 x 4096)
    sgemm_kernel<2><<<dim3(DIM_ / 128, ROWS / 128), 256>>>(
        hb, W2, out, ROWS, DIM_, DFF_, ff_gate, xb);
}

// round 3
// speedup vs baseline: 2.2673x; 2.2673x over previous
#include <cuda_runtime.h>
#include <cuda_bf16.h>
#include <math.h>
#include <stdint.h>

// ---------------------------------------------------------------------------
// Problem constants
// ---------------------------------------------------------------------------
#define B_     4
#define T1_    2048
#define JT_    512
#define DIM_   1024
#define INNER_ 512
#define DFF_   4096
#define H_     8
#define DH_    64

// ---------------------------------------------------------------------------
// Scratch (device globals; no allocation allowed)
// ---------------------------------------------------------------------------
__device__ float g_lnbuf[(size_t)B_*T1_*DIM_];
__device__ float g_q   [(size_t)B_*T1_*INNER_];
__device__ float g_kv  [(size_t)B_*JT_*2*INNER_];
__device__ float g_ao  [(size_t)B_*T1_*INNER_];
__device__ float g_x   [(size_t)B_*T1_*DIM_];
__device__ float g_h   [(size_t)B_*T1_*DFF_];
__device__ int   g_mask_mode;

// ---------------------------------------------------------------------------
// Mask dtype detection (bool may arrive as uint8 / int32 / float32)
// ---------------------------------------------------------------------------
__global__ void detect_mask_kernel(const unsigned int* __restrict__ w, int nwords)
{
    __shared__ int f_u8, f_f32;
    if (threadIdx.x == 0) { f_u8 = 0; f_f32 = 0; }
    __syncthreads();
    int u8 = 0, f32 = 0;
    for (int i = threadIdx.x; i < nwords; i += blockDim.x) {
        unsigned int x = w[i];
        if (x == 0x3F800000u)            f32 = 1;
        else if (x != 0u && x != 1u)     u8  = 1;
    }
    if (u8)  atomicOr(&f_u8, 1);
    if (f32) atomicOr(&f_f32, 1);
    __syncthreads();
    if (threadIdx.x == 0)
        g_mask_mode = f_u8 ? 0 : (f_f32 ? 2 : 1);
}

__device__ __forceinline__ bool read_mask(const void* p, size_t i, int mode)
{
    if (mode == 1) return ((const int*)p)[i] != 0;
    if (mode == 2) return ((const float*)p)[i] != 0.0f;
    return ((const unsigned char*)p)[i] != 0;
}

// ---------------------------------------------------------------------------
// LayerNorm over last dim (1024). One block per row, 256 threads.
// ---------------------------------------------------------------------------
__global__ __launch_bounds__(256) void ln_kernel(
    const float* __restrict__ x, const float* __restrict__ gw,
    const float* __restrict__ bw, float* __restrict__ y)
{
    const int row = blockIdx.x;
    const float* xr = x + (size_t)row * DIM_;
    float v[4];
    float s = 0.f, s2 = 0.f;
    #pragma unroll
    for (int k = 0; k < 4; k++) {
        v[k] = xr[threadIdx.x + k * 256];
        s += v[k]; s2 += v[k] * v[k];
    }
    #pragma unroll
    for (int o = 16; o; o >>= 1) {
        s  += __shfl_xor_sync(0xffffffffu, s,  o);
        s2 += __shfl_xor_sync(0xffffffffu, s2, o);
    }
    __shared__ float sh[2][8];
    const int warp = threadIdx.x >> 5, lane = threadIdx.x & 31;
    if (lane == 0) { sh[0][warp] = s; sh[1][warp] = s2; }
    __syncthreads();
    if (threadIdx.x == 0) {
        float S = 0.f, S2 = 0.f;
        #pragma unroll
        for (int w = 0; w < 8; w++) { S += sh[0][w]; S2 += sh[1][w]; }
        const float mu  = S  * (1.0f / DIM_);
        const float var = S2 * (1.0f / DIM_) - mu * mu;
        sh[0][0] = mu;
        sh[1][0] = rsqrtf(var + 1e-5f);
    }
    __syncthreads();
    const float mu = sh[0][0], inv = sh[1][0];
    float* yr = y + (size_t)row * DIM_;
    #pragma unroll
    for (int k = 0; k < 4; k++) {
        const int c = threadIdx.x + k * 256;
        yr[c] = (v[k] - mu) * inv * gw[c] + bw[c];
    }
}

// ---------------------------------------------------------------------------
// TF32 tensor-core GEMM via mma.sync.aligned.m16n8k8.
// 128x128x32 CTA tile, 256 threads = 8 warps as 4(m) x 2(n); warp tile 32x64
// = 2x8 m16n8k8 fragments. Double-buffered smem, register-staged global
// loads, cvt.rna.tf32 applied once per element at the staging store.
// smem layouts: A[row][k] pitch 36, B[k][col] pitch 136 -> staging stores and
// all fragment LDS patterns are bank-conflict-free.
// EPI: 0 = none, 1 = exact GELU, 2 = v*tanh(*gate) + res[r,c]
// ---------------------------------------------------------------------------
#define G_AP 36
#define G_BP 136
#define G_ASZ (128 * G_AP)
#define G_BSZ (32 * G_BP)
#define GEMM_SMEM ((2 * (G_ASZ + G_BSZ)) * (int)sizeof(float))

__device__ __forceinline__ float tf32r(float x)
{
    uint32_t r;
    asm("cvt.rna.tf32.f32 %0, %1;" : "=r"(r) : "f"(x));
    return __uint_as_float(r);
}

__device__ __forceinline__ void mma_tf32(
    float* c, const uint32_t* a, const uint32_t* b)
{
    asm volatile(
        "mma.sync.aligned.m16n8k8.row.col.f32.tf32.tf32.f32 "
        "{%0,%1,%2,%3},{%4,%5,%6,%7},{%8,%9},{%0,%1,%2,%3};"
        : "+f"(c[0]), "+f"(c[1]), "+f"(c[2]), "+f"(c[3])
        : "r"(a[0]), "r"(a[1]), "r"(a[2]), "r"(a[3]), "r"(b[0]), "r"(b[1]));
}

template <int EPI>
__global__ __launch_bounds__(256) void tf32_gemm_kernel(
    const float* __restrict__ A, const float* __restrict__ Bm,
    float* __restrict__ C, int M, int N, int K,
    const float* __restrict__ gate, const float* __restrict__ res)
{
    extern __shared__ float smp[];
    float* Abuf0 = smp;
    float* Bbuf0 = smp + G_ASZ;
    float* Abuf1 = smp + G_ASZ + G_BSZ;
    float* Bbuf1 = smp + 2 * G_ASZ + G_BSZ;

    const int tid  = threadIdx.x;
    const int warp = tid >> 5, lane = tid & 31;
    const int wm = warp >> 1, wn = warp & 1;
    const int g = lane >> 2, l4 = lane & 3;
    const int row0 = blockIdx.y << 7, col0 = blockIdx.x << 7;

    // global staging indices: A 128x32 (8 float4/row), B 32x128 (32 float4/row)
    const int ar = tid >> 3, ac = (tid & 7) << 2;
    const int br = tid >> 5, bc = (tid & 31) << 2;
    const float* Ag = A  + (size_t)(row0 + ar) * K + ac;
    const float* Bg = Bm + (size_t)br * N + col0 + bc;

    float4 ra[4], rb[4];

    float c[2][8][4];
    #pragma unroll
    for (int i = 0; i < 2; i++)
        #pragma unroll
        for (int j = 0; j < 8; j++)
            #pragma unroll
            for (int q = 0; q < 4; q++) c[i][j][q] = 0.f;

    const int iters = K >> 5;

    // prologue: tile 0
    #pragma unroll
    for (int i = 0; i < 4; i++)
        ra[i] = *reinterpret_cast<const float4*>(Ag + (size_t)(32 * i) * K);
    #pragma unroll
    for (int i = 0; i < 4; i++)
        rb[i] = *reinterpret_cast<const float4*>(Bg + (size_t)(8 * i) * N);
    #pragma unroll
    for (int i = 0; i < 4; i++) {
        float* p = Abuf0 + (ar + 32 * i) * G_AP + ac;
        p[0] = tf32r(ra[i].x); p[1] = tf32r(ra[i].y);
        p[2] = tf32r(ra[i].z); p[3] = tf32r(ra[i].w);
    }
    #pragma unroll
    for (int i = 0; i < 4; i++) {
        float* p = Bbuf0 + (br + 8 * i) * G_BP + bc;
        p[0] = tf32r(rb[i].x); p[1] = tf32r(rb[i].y);
        p[2] = tf32r(rb[i].z); p[3] = tf32r(rb[i].w);
    }
    __syncthreads();

    int cur = 0;
    for (int t = 0; t < iters; t++) {
        const int k1 = (t + 1) << 5;
        if (t + 1 < iters) {
            #pragma unroll
            for (int i = 0; i < 4; i++)
                ra[i] = *reinterpret_cast<const float4*>(Ag + (size_t)(32 * i) * K + k1);
            #pragma unroll
            for (int i = 0; i < 4; i++)
                rb[i] = *reinterpret_cast<const float4*>(Bg + (size_t)(k1 + 8 * i) * N);
        }

        const float* As = cur ? Abuf1 : Abuf0;
        const float* Bs = cur ? Bbuf1 : Bbuf0;
        #pragma unroll
        for (int ks = 0; ks < 4; ks++) {
            uint32_t a[2][4], b[8][2];
            #pragma unroll
            for (int i = 0; i < 2; i++) {
                const float* ap = As + (wm * 32 + i * 16 + g) * G_AP + ks * 8 + l4;
                a[i][0] = __float_as_uint(ap[0]);
                a[i][1] = __float_as_uint(ap[8 * G_AP]);
                a[i][2] = __float_as_uint(ap[4]);
                a[i][3] = __float_as_uint(ap[8 * G_AP + 4]);
            }
            const float* bp = Bs + (ks * 8 + l4) * G_BP + wn * 64 + g;
            #pragma unroll
            for (int j = 0; j < 8; j++) {
                b[j][0] = __float_as_uint(bp[j * 8]);
                b[j][1] = __float_as_uint(bp[4 * G_BP + j * 8]);
            }
            #pragma unroll
            for (int i = 0; i < 2; i++)
                #pragma unroll
                for (int j = 0; j < 8; j++)
                    mma_tf32(c[i][j], a[i], b[j]);
        }

        if (t + 1 < iters) {
            float* Ad = cur ? Abuf0 : Abuf1;
            float* Bd = cur ? Bbuf0 : Bbuf1;
            #pragma unroll
            for (int i = 0; i < 4; i++) {
                float* p = Ad + (ar + 32 * i) * G_AP + ac;
                p[0] = tf32r(ra[i].x); p[1] = tf32r(ra[i].y);
                p[2] = tf32r(ra[i].z); p[3] = tf32r(ra[i].w);
            }
            #pragma unroll
            for (int i = 0; i < 4; i++) {
                float* p = Bd + (br + 8 * i) * G_BP + bc;
                p[0] = tf32r(rb[i].x); p[1] = tf32r(rb[i].y);
                p[2] = tf32r(rb[i].z); p[3] = tf32r(rb[i].w);
            }
        }
        __syncthreads();
        cur ^= 1;
    }

    // epilogue + writeback (c0,c1 -> row r, cols 2*l4,2*l4+1; c2,c3 -> row r+8)
    float gt = 0.f;
    if (EPI == 2) gt = tanhf(gate[0]);
    #pragma unroll
    for (int i = 0; i < 2; i++) {
        const int r_lo = row0 + wm * 32 + i * 16 + g;
        #pragma unroll
        for (int j = 0; j < 8; j++) {
            const int cc = col0 + wn * 64 + j * 8 + 2 * l4;
            #pragma unroll
            for (int half = 0; half < 2; half++) {
                const size_t rr = (size_t)(r_lo + 8 * half);
                float v0 = c[i][j][2 * half + 0];
                float v1 = c[i][j][2 * half + 1];
                if (EPI == 1) {
                    v0 = 0.5f * v0 * (1.0f + erff(v0 * 0.70710678118654752f));
                    v1 = 0.5f * v1 * (1.0f + erff(v1 * 0.70710678118654752f));
                }
                if (EPI == 2) {
                    v0 = v0 * gt + res[rr * N + cc];
                    v1 = v1 * gt + res[rr * N + cc + 1];
                }
                float2 o = make_float2(v0, v1);
                *reinterpret_cast<float2*>(C + rr * N + cc) = o;
            }
        }
    }
}

// ---------------------------------------------------------------------------
// Fused masked cross-attention (unchanged from R1).
// ---------------------------------------------------------------------------
#define ATTN_PAD 68
#define ATTN_SMEM ((64 + 128 + 128) * ATTN_PAD * 4 + 128)

__global__ __launch_bounds__(256) void attn_kernel(
    const float* __restrict__ Q,
    const float* __restrict__ KV,
    const void*  __restrict__ amask,
    const void*  __restrict__ kvmask,
    const float* __restrict__ qmask,
    float* __restrict__ AO)
{
    extern __shared__ float sm[];
    float* Qs = sm;
    float* Ks = sm + 64 * ATTN_PAD;
    float* Vs = Ks + 128 * ATTN_PAD;
    unsigned char* kvm = (unsigned char*)(Vs + 128 * ATTN_PAD);

    const int i0 = blockIdx.x * 64;
    const int h  = blockIdx.y;
    const int b  = blockIdx.z;
    const int tid = threadIdx.x;
    const int r = tid >> 2, sub = tid & 3;
    const int mode = g_mask_mode;

    for (int t = tid; t < 64 * 16; t += 256) {
        const int rr = t >> 4, c4 = (t & 15) << 2;
        const float4 qv = *reinterpret_cast<const float4*>(
            Q + ((size_t)(b * T1_ + i0 + rr)) * INNER_ + h * DH_ + c4);
        float* dst = Qs + rr * ATTN_PAD + c4;
        dst[0] = qv.x * 0.125f; dst[1] = qv.y * 0.125f;
        dst[2] = qv.z * 0.125f; dst[3] = qv.w * 0.125f;
    }

    float m = -1e38f, l = 0.f;
    float acc[64];
    #pragma unroll
    for (int d = 0; d < 64; d++) acc[d] = 0.f;

    const size_t am_base = ((size_t)(b * T1_ + i0 + r)) * JT_;

    for (int kt = 0; kt < 4; kt++) {
        __syncthreads();
        for (int t = tid; t < 128 * 16; t += 256) {
            const int rr = t >> 4, c4 = (t & 15) << 2;
            const float* kp = KV + ((size_t)(b * JT_ + kt * 128 + rr)) * (2 * INNER_)
                                 + h * DH_ + c4;
            const float4 k4 = *reinterpret_cast<const float4*>(kp);
            const float4 v4 = *reinterpret_cast<const float4*>(kp + INNER_);
            float* kd = Ks + rr * ATTN_PAD + c4;
            kd[0] = k4.x; kd[1] = k4.y; kd[2] = k4.z; kd[3] = k4.w;
            float* vd = Vs + rr * ATTN_PAD + c4;
            vd[0] = v4.x; vd[1] = v4.y; vd[2] = v4.z; vd[3] = v4.w;
        }
        if (tid < 128)
            kvm[tid] = read_mask(kvmask, (size_t)b * JT_ + kt * 128 + tid, mode) ? 1 : 0;
        __syncthreads();

        float s[32];
        unsigned keep = 0u;
        float tmax = -1e38f;
        #pragma unroll
        for (int jj = 0; jj < 32; jj++) {
            const int jl = (jj << 2) + sub;
            s[jj] = 0.f;
            if (kvm[jl] && read_mask(amask, am_base + kt * 128 + jl, mode)) {
                float sv = 0.f;
                const float* qp = Qs + r * ATTN_PAD;
                const float* kp = Ks + jl * ATTN_PAD;
                #pragma unroll
                for (int d = 0; d < 64; d++) sv = fmaf(qp[d], kp[d], sv);
                s[jj] = sv;
                keep |= (1u << jj);
                tmax = fmaxf(tmax, sv);
            }
        }
        if (!keep) continue;

        const float mn = fmaxf(m, tmax);
        const float alpha = (m > -1e37f) ? __expf(m - mn) : 0.f;
        l *= alpha;
        #pragma unroll
        for (int d = 0; d < 64; d++) acc[d] *= alpha;
        #pragma unroll
        for (int jj = 0; jj < 32; jj++) {
            if (!((keep >> jj) & 1u)) continue;
            const float p = __expf(s[jj] - mn);
            l += p;
            const float* vp = Vs + ((jj << 2) + sub) * ATTN_PAD;
            #pragma unroll
            for (int d = 0; d < 64; d++) acc[d] = fmaf(p, vp[d], acc[d]);
        }
        m = mn;
    }

    float mAll = m;
    mAll = fmaxf(mAll, __shfl_xor_sync(0xffffffffu, mAll, 1));
    mAll = fmaxf(mAll, __shfl_xor_sync(0xffffffffu, mAll, 2));
    const float alpha = (m > -1e37f) ? __expf(m - mAll) : 0.f;
    float lw = l * alpha;
    lw += __shfl_xor_sync(0xffffffffu, lw, 1);
    lw += __shfl_xor_sync(0xffffffffu, lw, 2);
    const float scale = (lw > 0.f) ? qmask[b * T1_ + i0 + r] / lw : 0.f;

    float* dst = AO + ((size_t)(b * T1_ + i0 + r)) * INNER_ + h * DH_;
    #pragma unroll
    for (int d = 0; d < 64; d++) {
        float a = acc[d] * alpha;
        a += __shfl_xor_sync(0xffffffffu, a, 1);
        a += __shfl_xor_sync(0xffffffffu, a, 2);
        if ((d >> 4) == sub) dst[d] = a * scale;
    }
}

// ---------------------------------------------------------------------------
// kernel_launch
// ---------------------------------------------------------------------------
extern "C" void kernel_launch(void* const* d_in, const int* in_sizes, int n_in,
                              void* d_out, int out_size)
{
    const float* qo        = (const float*)d_in[0];
    const float* kvo       = (const float*)d_in[1];
    const void*  amask     = d_in[2];
    const float* qmask     = (const float*)d_in[3];
    const void*  kvmask    = d_in[4];
    const float* ln_g      = (const float*)d_in[5];
    const float* ln_b      = (const float*)d_in[6];
    const float* Wq        = (const float*)d_in[7];
    const float* Wkv       = (const float*)d_in[8];
    const float* Wout      = (const float*)d_in[9];
    const float* attn_gate = (const float*)d_in[10];
    const float* ff_ln_g   = (const float*)d_in[11];
    const float* ff_ln_b   = (const float*)d_in[12];
    const float* W1        = (const float*)d_in[13];
    const float* W2        = (const float*)d_in[14];
    const float* ff_gate   = (const float*)d_in[15];
    float* out = (float*)d_out;

    float *lnbuf, *qb, *kvb, *aob, *xb, *hb;
    cudaGetSymbolAddress((void**)&lnbuf, g_lnbuf);
    cudaGetSymbolAddress((void**)&qb,    g_q);
    cudaGetSymbolAddress((void**)&kvb,   g_kv);
    cudaGetSymbolAddress((void**)&aob,   g_ao);
    cudaGetSymbolAddress((void**)&xb,    g_x);
    cudaGetSymbolAddress((void**)&hb,    g_h);

    cudaFuncSetAttribute(tf32_gemm_kernel<0>,
        cudaFuncAttributeMaxDynamicSharedMemorySize, GEMM_SMEM);
    cudaFuncSetAttribute(tf32_gemm_kernel<1>,
        cudaFuncAttributeMaxDynamicSharedMemorySize, GEMM_SMEM);
    cudaFuncSetAttribute(tf32_gemm_kernel<2>,
        cudaFuncAttributeMaxDynamicSharedMemorySize, GEMM_SMEM);
    cudaFuncSetAttribute(attn_kernel,
        cudaFuncAttributeMaxDynamicSharedMemorySize, ATTN_SMEM);

    detect_mask_kernel<<<1, 256>>>((const unsigned int*)amask, 2048);

    const int ROWS = B_ * T1_;   // 8192

    // 1) LN(qo)
    ln_kernel<<<ROWS, 256>>>(qo, ln_g, ln_b, lnbuf);
    // 2) q = LN(qo) @ Wq        (8192 x 512 x 1024)
    tf32_gemm_kernel<0><<<dim3(INNER_ / 128, ROWS / 128), 256, GEMM_SMEM>>>(
        lnbuf, Wq, qb, ROWS, INNER_, DIM_, nullptr, nullptr);
    // 3) kv = kvo_flat @ Wkv    (2048 x 1024 x 1024)
    tf32_gemm_kernel<0><<<dim3((2 * INNER_) / 128, (B_ * JT_) / 128), 256, GEMM_SMEM>>>(
        kvo, Wkv, kvb, B_ * JT_, 2 * INNER_, DIM_, nullptr, nullptr);
    // 4) fused masked attention -> g_ao
    attn_kernel<<<dim3(T1_ / 64, H_, B_), 256, ATTN_SMEM>>>(
        qb, kvb, amask, kvmask, qmask, aob);
    // 5) x = (ao @ Wout) * tanh(attn_gate) + qo   (8192 x 1024 x 512)
    tf32_gemm_kernel<2><<<dim3(DIM_ / 128, ROWS / 128), 256, GEMM_SMEM>>>(
        aob, Wout, xb, ROWS, DIM_, INNER_, attn_gate, qo);
    // 6) LN(x)
    ln_kernel<<<ROWS, 256>>>(xb, ff_ln_g, ff_ln_b, lnbuf);
    // 7) h = gelu(LN(x) @ W1)   (8192 x 4096 x 1024)
    tf32_gemm_kernel<1><<<dim3(DFF_ / 128, ROWS / 128), 256, GEMM_SMEM>>>(
        lnbuf, W1, hb, ROWS, DFF_, DIM_, nullptr, nullptr);
    // 8) out = (h @ W2) * tanh(ff_gate) + x   (8192 x 1024 x 4096)
    tf32_gemm_kernel<2><<<dim3(DIM_ / 128, ROWS / 128), 256, GEMM_SMEM>>>(
        hb, W2, out, ROWS, DIM_, DFF_, ff_gate, xb);
}

// round 4
// speedup vs baseline: 2.5778x; 1.1369x over previous
#include <cuda_runtime.h>
#include <cuda_bf16.h>
#include <math.h>
#include <stdint.h>

// ---------------------------------------------------------------------------
// Problem constants
// ---------------------------------------------------------------------------
#define B_     4
#define T1_    2048
#define JT_    512
#define DIM_   1024
#define INNER_ 512
#define DFF_   4096
#define H_     8
#define DH_    64

// ---------------------------------------------------------------------------
// Scratch (device globals; no allocation allowed)
// ---------------------------------------------------------------------------
__device__ float g_lnbuf[(size_t)B_*T1_*DIM_];
__device__ float g_q   [(size_t)B_*T1_*INNER_];
__device__ float g_kv  [(size_t)B_*JT_*2*INNER_];
__device__ float g_ao  [(size_t)B_*T1_*INNER_];
__device__ float g_x   [(size_t)B_*T1_*DIM_];
__device__ float g_h   [(size_t)B_*T1_*DFF_];
__device__ int   g_mask_mode;

// ---------------------------------------------------------------------------
// Mask dtype detection (bool may arrive as uint8 / int32 / float32)
// ---------------------------------------------------------------------------
__global__ void detect_mask_kernel(const unsigned int* __restrict__ w, int nwords)
{
    __shared__ int f_u8, f_f32;
    if (threadIdx.x == 0) { f_u8 = 0; f_f32 = 0; }
    __syncthreads();
    int u8 = 0, f32 = 0;
    for (int i = threadIdx.x; i < nwords; i += blockDim.x) {
        unsigned int x = w[i];
        if (x == 0x3F800000u)            f32 = 1;
        else if (x != 0u && x != 1u)     u8  = 1;
    }
    if (u8)  atomicOr(&f_u8, 1);
    if (f32) atomicOr(&f_f32, 1);
    __syncthreads();
    if (threadIdx.x == 0)
        g_mask_mode = f_u8 ? 0 : (f_f32 ? 2 : 1);
}

__device__ __forceinline__ bool read_mask(const void* p, size_t i, int mode)
{
    if (mode == 1) return ((const int*)p)[i] != 0;
    if (mode == 2) return ((const float*)p)[i] != 0.0f;
    return ((const unsigned char*)p)[i] != 0;
}

// ---------------------------------------------------------------------------
// LayerNorm over last dim (1024). One block per row, 256 threads.
// ---------------------------------------------------------------------------
__global__ __launch_bounds__(256) void ln_kernel(
    const float* __restrict__ x, const float* __restrict__ gw,
    const float* __restrict__ bw, float* __restrict__ y)
{
    const int row = blockIdx.x;
    const float* xr = x + (size_t)row * DIM_;
    float v[4];
    float s = 0.f, s2 = 0.f;
    #pragma unroll
    for (int k = 0; k < 4; k++) {
        v[k] = xr[threadIdx.x + k * 256];
        s += v[k]; s2 += v[k] * v[k];
    }
    #pragma unroll
    for (int o = 16; o; o >>= 1) {
        s  += __shfl_xor_sync(0xffffffffu, s,  o);
        s2 += __shfl_xor_sync(0xffffffffu, s2, o);
    }
    __shared__ float sh[2][8];
    const int warp = threadIdx.x >> 5, lane = threadIdx.x & 31;
    if (lane == 0) { sh[0][warp] = s; sh[1][warp] = s2; }
    __syncthreads();
    if (threadIdx.x == 0) {
        float S = 0.f, S2 = 0.f;
        #pragma unroll
        for (int w = 0; w < 8; w++) { S += sh[0][w]; S2 += sh[1][w]; }
        const float mu  = S  * (1.0f / DIM_);
        const float var = S2 * (1.0f / DIM_) - mu * mu;
        sh[0][0] = mu;
        sh[1][0] = rsqrtf(var + 1e-5f);
    }
    __syncthreads();
    const float mu = sh[0][0], inv = sh[1][0];
    float* yr = y + (size_t)row * DIM_;
    #pragma unroll
    for (int k = 0; k < 4; k++) {
        const int c = threadIdx.x + k * 256;
        yr[c] = (v[k] - mu) * inv * gw[c] + bw[c];
    }
}

// ---------------------------------------------------------------------------
// TF32 helpers
// ---------------------------------------------------------------------------
__device__ __forceinline__ float tf32r(float x)
{
    uint32_t r;
    asm("cvt.rna.tf32.f32 %0, %1;" : "=r"(r) : "f"(x));
    return __uint_as_float(r);
}

__device__ __forceinline__ void mma_tf32(
    float* c, const uint32_t* a, const uint32_t* b)
{
    asm volatile(
        "mma.sync.aligned.m16n8k8.row.col.f32.tf32.tf32.f32 "
        "{%0,%1,%2,%3},{%4,%5,%6,%7},{%8,%9},{%0,%1,%2,%3};"
        : "+f"(c[0]), "+f"(c[1]), "+f"(c[2]), "+f"(c[3])
        : "r"(a[0]), "r"(a[1]), "r"(a[2]), "r"(a[3]), "r"(b[0]), "r"(b[1]));
}

// ---------------------------------------------------------------------------
// TF32 tensor-core GEMM (unchanged from R3, validated).
// ---------------------------------------------------------------------------
#define G_AP 36
#define G_BP 136
#define G_ASZ (128 * G_AP)
#define G_BSZ (32 * G_BP)
#define GEMM_SMEM ((2 * (G_ASZ + G_BSZ)) * (int)sizeof(float))

template <int EPI>
__global__ __launch_bounds__(256) void tf32_gemm_kernel(
    const float* __restrict__ A, const float* __restrict__ Bm,
    float* __restrict__ C, int M, int N, int K,
    const float* __restrict__ gate, const float* __restrict__ res)
{
    extern __shared__ float smp[];
    float* Abuf0 = smp;
    float* Bbuf0 = smp + G_ASZ;
    float* Abuf1 = smp + G_ASZ + G_BSZ;
    float* Bbuf1 = smp + 2 * G_ASZ + G_BSZ;

    const int tid  = threadIdx.x;
    const int warp = tid >> 5, lane = tid & 31;
    const int wm = warp >> 1, wn = warp & 1;
    const int g = lane >> 2, l4 = lane & 3;
    const int row0 = blockIdx.y << 7, col0 = blockIdx.x << 7;

    const int ar = tid >> 3, ac = (tid & 7) << 2;
    const int br = tid >> 5, bc = (tid & 31) << 2;
    const float* Ag = A  + (size_t)(row0 + ar) * K + ac;
    const float* Bg = Bm + (size_t)br * N + col0 + bc;

    float4 ra[4], rb[4];

    float c[2][8][4];
    #pragma unroll
    for (int i = 0; i < 2; i++)
        #pragma unroll
        for (int j = 0; j < 8; j++)
            #pragma unroll
            for (int q = 0; q < 4; q++) c[i][j][q] = 0.f;

    const int iters = K >> 5;

    #pragma unroll
    for (int i = 0; i < 4; i++)
        ra[i] = *reinterpret_cast<const float4*>(Ag + (size_t)(32 * i) * K);
    #pragma unroll
    for (int i = 0; i < 4; i++)
        rb[i] = *reinterpret_cast<const float4*>(Bg + (size_t)(8 * i) * N);
    #pragma unroll
    for (int i = 0; i < 4; i++) {
        float* p = Abuf0 + (ar + 32 * i) * G_AP + ac;
        p[0] = tf32r(ra[i].x); p[1] = tf32r(ra[i].y);
        p[2] = tf32r(ra[i].z); p[3] = tf32r(ra[i].w);
    }
    #pragma unroll
    for (int i = 0; i < 4; i++) {
        float* p = Bbuf0 + (br + 8 * i) * G_BP + bc;
        p[0] = tf32r(rb[i].x); p[1] = tf32r(rb[i].y);
        p[2] = tf32r(rb[i].z); p[3] = tf32r(rb[i].w);
    }
    __syncthreads();

    int cur = 0;
    for (int t = 0; t < iters; t++) {
        const int k1 = (t + 1) << 5;
        if (t + 1 < iters) {
            #pragma unroll
            for (int i = 0; i < 4; i++)
                ra[i] = *reinterpret_cast<const float4*>(Ag + (size_t)(32 * i) * K + k1);
            #pragma unroll
            for (int i = 0; i < 4; i++)
                rb[i] = *reinterpret_cast<const float4*>(Bg + (size_t)(k1 + 8 * i) * N);
        }

        const float* As = cur ? Abuf1 : Abuf0;
        const float* Bs = cur ? Bbuf1 : Bbuf0;
        #pragma unroll
        for (int ks = 0; ks < 4; ks++) {
            uint32_t a[2][4], b[8][2];
            #pragma unroll
            for (int i = 0; i < 2; i++) {
                const float* ap = As + (wm * 32 + i * 16 + g) * G_AP + ks * 8 + l4;
                a[i][0] = __float_as_uint(ap[0]);
                a[i][1] = __float_as_uint(ap[8 * G_AP]);
                a[i][2] = __float_as_uint(ap[4]);
                a[i][3] = __float_as_uint(ap[8 * G_AP + 4]);
            }
            const float* bp = Bs + (ks * 8 + l4) * G_BP + wn * 64 + g;
            #pragma unroll
            for (int j = 0; j < 8; j++) {
                b[j][0] = __float_as_uint(bp[j * 8]);
                b[j][1] = __float_as_uint(bp[4 * G_BP + j * 8]);
            }
            #pragma unroll
            for (int i = 0; i < 2; i++)
                #pragma unroll
                for (int j = 0; j < 8; j++)
                    mma_tf32(c[i][j], a[i], b[j]);
        }

        if (t + 1 < iters) {
            float* Ad = cur ? Abuf0 : Abuf1;
            float* Bd = cur ? Bbuf0 : Bbuf1;
            #pragma unroll
            for (int i = 0; i < 4; i++) {
                float* p = Ad + (ar + 32 * i) * G_AP + ac;
                p[0] = tf32r(ra[i].x); p[1] = tf32r(ra[i].y);
                p[2] = tf32r(ra[i].z); p[3] = tf32r(ra[i].w);
            }
            #pragma unroll
            for (int i = 0; i < 4; i++) {
                float* p = Bd + (br + 8 * i) * G_BP + bc;
                p[0] = tf32r(rb[i].x); p[1] = tf32r(rb[i].y);
                p[2] = tf32r(rb[i].z); p[3] = tf32r(rb[i].w);
            }
        }
        __syncthreads();
        cur ^= 1;
    }

    float gt = 0.f;
    if (EPI == 2) gt = tanhf(gate[0]);
    #pragma unroll
    for (int i = 0; i < 2; i++) {
        const int r_lo = row0 + wm * 32 + i * 16 + g;
        #pragma unroll
        for (int j = 0; j < 8; j++) {
            const int cc = col0 + wn * 64 + j * 8 + 2 * l4;
            #pragma unroll
            for (int half = 0; half < 2; half++) {
                const size_t rr = (size_t)(r_lo + 8 * half);
                float v0 = c[i][j][2 * half + 0];
                float v1 = c[i][j][2 * half + 1];
                if (EPI == 1) {
                    v0 = 0.5f * v0 * (1.0f + erff(v0 * 0.70710678118654752f));
                    v1 = 0.5f * v1 * (1.0f + erff(v1 * 0.70710678118654752f));
                }
                if (EPI == 2) {
                    v0 = v0 * gt + res[rr * N + cc];
                    v1 = v1 * gt + res[rr * N + cc + 1];
                }
                float2 o = make_float2(v0, v1);
                *reinterpret_cast<float2*>(C + rr * N + cc) = o;
            }
        }
    }
}

// ---------------------------------------------------------------------------
// NEW: mma-based fused masked flash attention.
// CTA = (64 query rows, head h, batch b); 128 threads = 4 warps x 16 rows.
// j-loop over 4 tiles of 128 keys:
//   S = Qscaled @ K^T via m16n8k8.tf32 (Q frags in regs, K in smem pitch-68)
//   mask -> online softmax on S fragments (quad shfl row-reductions)
//   P (tf32) relaid C-frag -> A-frag via quad shfls; O += P @ V via mma.
// Dead rows (no keys) produce exact zeros. Output multiplied by q_mask.
// ---------------------------------------------------------------------------
#define AT_PAD  68
#define KEEP_P  132
#define AT_QS   (64 * AT_PAD)
#define AT_KS   (128 * AT_PAD)
#define AT_VS   (128 * AT_PAD)
#define ATTN2_SMEM (((AT_QS + AT_KS + AT_VS) * 4) + 64 * KEEP_P)

__global__ __launch_bounds__(128) void attn_mma_kernel(
    const float* __restrict__ Q,
    const float* __restrict__ KV,
    const void*  __restrict__ amask,
    const void*  __restrict__ kvmask,
    const float* __restrict__ qmask,
    float* __restrict__ AO)
{
    extern __shared__ float sm[];
    float* Qs = sm;                                   // 64 x 68
    float* Ks = Qs + AT_QS;                           // 128 x 68
    float* Vs = Ks + AT_KS;                           // 128 x 68
    unsigned char* keep = (unsigned char*)(Vs + AT_VS); // 64 x 132

    const int i0 = blockIdx.x * 64;
    const int h  = blockIdx.y;
    const int b  = blockIdx.z;
    const int tid  = threadIdx.x;
    const int warp = tid >> 5, lane = tid & 31;
    const int g = lane >> 2, q4 = lane & 3;
    const int mode = g_mask_mode;
    const int row_g = warp * 16 + g;                  // local rows row_g, row_g+8

    // stage Q (64 x 64), pre-scaled by DH^-0.5
    for (int t = tid; t < 64 * 16; t += 128) {
        const int rr = t >> 4, c4 = (t & 15) << 2;
        const float4 v = *reinterpret_cast<const float4*>(
            Q + ((size_t)(b * T1_ + i0 + rr)) * INNER_ + h * DH_ + c4);
        float* d = Qs + rr * AT_PAD + c4;
        d[0] = v.x * 0.125f; d[1] = v.y * 0.125f;
        d[2] = v.z * 0.125f; d[3] = v.w * 0.125f;
    }

    float m0 = -1e38f, m1 = -1e38f, l0 = 0.f, l1 = 0.f;
    float o[8][4];
    #pragma unroll
    for (int j = 0; j < 8; j++)
        #pragma unroll
        for (int q = 0; q < 4; q++) o[j][q] = 0.f;

    for (int kt = 0; kt < 4; kt++) {
        __syncthreads();   // smem (incl. Qs on first pass) ready / consumed

        // stage K,V tile (128 keys x 64), tf32-rounded
        for (int t = tid; t < 128 * 16; t += 128) {
            const int rr = t >> 4, c4 = (t & 15) << 2;
            const float* kp = KV + ((size_t)(b * JT_ + kt * 128 + rr)) * (2 * INNER_)
                                 + h * DH_ + c4;
            const float4 k4 = *reinterpret_cast<const float4*>(kp);
            const float4 v4 = *reinterpret_cast<const float4*>(kp + INNER_);
            float* kd = Ks + rr * AT_PAD + c4;
            kd[0] = tf32r(k4.x); kd[1] = tf32r(k4.y);
            kd[2] = tf32r(k4.z); kd[3] = tf32r(k4.w);
            float* vd = Vs + rr * AT_PAD + c4;
            vd[0] = tf32r(v4.x); vd[1] = tf32r(v4.y);
            vd[2] = tf32r(v4.z); vd[3] = tf32r(v4.w);
        }
        // stage combined keep bytes (64 rows x 128 cols)
        for (int t = tid; t < 64 * 128; t += 128) {
            const int rr = t >> 7, cc = t & 127;
            const bool a = read_mask(amask,
                ((size_t)(b * T1_ + i0 + rr)) * JT_ + kt * 128 + cc, mode);
            const bool k = read_mask(kvmask, (size_t)b * JT_ + kt * 128 + cc, mode);
            keep[rr * KEEP_P + cc] = (a && k) ? 1 : 0;
        }
        __syncthreads();

        // Q fragments for this warp (regs; reloaded per tile to cap pressure)
        uint32_t qa[8][4];
        #pragma unroll
        for (int ks = 0; ks < 8; ks++) {
            const float* base = Qs + (warp * 16) * AT_PAD + ks * 8 + q4;
            qa[ks][0] = __float_as_uint(tf32r(base[g * AT_PAD]));
            qa[ks][1] = __float_as_uint(tf32r(base[(g + 8) * AT_PAD]));
            qa[ks][2] = __float_as_uint(tf32r(base[g * AT_PAD + 4]));
            qa[ks][3] = __float_as_uint(tf32r(base[(g + 8) * AT_PAD + 4]));
        }

        // S = Q @ K^T : 16 n8-frags x 8 k-steps
        float sfr[16][4];
        #pragma unroll
        for (int j = 0; j < 16; j++)
            #pragma unroll
            for (int q = 0; q < 4; q++) sfr[j][q] = 0.f;
        #pragma unroll
        for (int ks = 0; ks < 8; ks++) {
            #pragma unroll
            for (int j = 0; j < 16; j++) {
                uint32_t bb[2];
                const float* kp = Ks + (j * 8 + g) * AT_PAD + ks * 8 + q4;
                bb[0] = __float_as_uint(kp[0]);
                bb[1] = __float_as_uint(kp[4]);
                mma_tf32(sfr[j], qa[ks], bb);
            }
        }

        // mask + per-tile row max
        const unsigned char* kr0 = keep + row_g * KEEP_P;
        const unsigned char* kr1 = kr0 + 8 * KEEP_P;
        float mt0 = -1e30f, mt1 = -1e30f;
        #pragma unroll
        for (int j = 0; j < 16; j++) {
            const int c0 = j * 8 + 2 * q4;
            sfr[j][0] = kr0[c0]     ? sfr[j][0] : -1e30f;
            sfr[j][1] = kr0[c0 + 1] ? sfr[j][1] : -1e30f;
            sfr[j][2] = kr1[c0]     ? sfr[j][2] : -1e30f;
            sfr[j][3] = kr1[c0 + 1] ? sfr[j][3] : -1e30f;
            mt0 = fmaxf(mt0, fmaxf(sfr[j][0], sfr[j][1]));
            mt1 = fmaxf(mt1, fmaxf(sfr[j][2], sfr[j][3]));
        }
        mt0 = fmaxf(mt0, __shfl_xor_sync(0xffffffffu, mt0, 1));
        mt0 = fmaxf(mt0, __shfl_xor_sync(0xffffffffu, mt0, 2));
        mt1 = fmaxf(mt1, __shfl_xor_sync(0xffffffffu, mt1, 1));
        mt1 = fmaxf(mt1, __shfl_xor_sync(0xffffffffu, mt1, 2));

        const float mn0 = fmaxf(m0, mt0), mn1 = fmaxf(m1, mt1);
        const float al0 = (m0 > -1e37f) ? __expf(m0 - mn0) : 0.f;
        const float al1 = (m1 > -1e37f) ? __expf(m1 - mn1) : 0.f;

        // p = exp(s - mn) with explicit keep predicate; tf32-round in place
        float ps0 = 0.f, ps1 = 0.f;
        #pragma unroll
        for (int j = 0; j < 16; j++) {
            float p0 = (sfr[j][0] > -1e29f) ? __expf(sfr[j][0] - mn0) : 0.f;
            float p1 = (sfr[j][1] > -1e29f) ? __expf(sfr[j][1] - mn0) : 0.f;
            float p2 = (sfr[j][2] > -1e29f) ? __expf(sfr[j][2] - mn1) : 0.f;
            float p3 = (sfr[j][3] > -1e29f) ? __expf(sfr[j][3] - mn1) : 0.f;
            ps0 += p0 + p1; ps1 += p2 + p3;
            sfr[j][0] = tf32r(p0); sfr[j][1] = tf32r(p1);
            sfr[j][2] = tf32r(p2); sfr[j][3] = tf32r(p3);
        }
        ps0 += __shfl_xor_sync(0xffffffffu, ps0, 1);
        ps0 += __shfl_xor_sync(0xffffffffu, ps0, 2);
        ps1 += __shfl_xor_sync(0xffffffffu, ps1, 1);
        ps1 += __shfl_xor_sync(0xffffffffu, ps1, 2);
        l0 = l0 * al0 + ps0;
        l1 = l1 * al1 + ps1;
        m0 = mn0; m1 = mn1;

        // rescale O
        #pragma unroll
        for (int j = 0; j < 8; j++) {
            o[j][0] *= al0; o[j][1] *= al0;
            o[j][2] *= al1; o[j][3] *= al1;
        }

        // O += P @ V : 16 k-steps; A-frag assembled from sfr via quad shfls
        const int srcA = (lane & ~3) | (q4 >> 1);
        const int srcB = srcA + 2;
        const bool odd = (q4 & 1);
        #pragma unroll
        for (int ks = 0; ks < 16; ks++) {
            const float v0a = __shfl_sync(0xffffffffu, sfr[ks][0], srcA);
            const float v1a = __shfl_sync(0xffffffffu, sfr[ks][1], srcA);
            const float v0b = __shfl_sync(0xffffffffu, sfr[ks][0], srcB);
            const float v1b = __shfl_sync(0xffffffffu, sfr[ks][1], srcB);
            const float w0a = __shfl_sync(0xffffffffu, sfr[ks][2], srcA);
            const float w1a = __shfl_sync(0xffffffffu, sfr[ks][3], srcA);
            const float w0b = __shfl_sync(0xffffffffu, sfr[ks][2], srcB);
            const float w1b = __shfl_sync(0xffffffffu, sfr[ks][3], srcB);
            uint32_t a[4];
            a[0] = __float_as_uint(odd ? v1a : v0a);   // (row g,   col q4)
            a[1] = __float_as_uint(odd ? w1a : w0a);   // (row g+8, col q4)
            a[2] = __float_as_uint(odd ? v1b : v0b);   // (row g,   col q4+4)
            a[3] = __float_as_uint(odd ? w1b : w0b);   // (row g+8, col q4+4)
            const float* vb = Vs + (ks * 8 + q4) * AT_PAD;
            #pragma unroll
            for (int j2 = 0; j2 < 8; j2++) {
                uint32_t bb[2];
                bb[0] = __float_as_uint(vb[j2 * 8 + g]);
                bb[1] = __float_as_uint(vb[4 * AT_PAD + j2 * 8 + g]);
                mma_tf32(o[j2], a, bb);
            }
        }
    }

    // finalize: divide by l (dead rows -> 0), apply q_mask, store
    const float qm0 = qmask[b * T1_ + i0 + row_g];
    const float qm1 = qmask[b * T1_ + i0 + row_g + 8];
    const float inv0 = (l0 > 0.f) ? qm0 / l0 : 0.f;
    const float inv1 = (l1 > 0.f) ? qm1 / l1 : 0.f;
    float* dst0 = AO + ((size_t)(b * T1_ + i0 + row_g)) * INNER_ + h * DH_;
    float* dst1 = dst0 + (size_t)8 * INNER_;
    #pragma unroll
    for (int j2 = 0; j2 < 8; j2++) {
        const int cc = j2 * 8 + 2 * q4;
        *reinterpret_cast<float2*>(dst0 + cc) =
            make_float2(o[j2][0] * inv0, o[j2][1] * inv0);
        *reinterpret_cast<float2*>(dst1 + cc) =
            make_float2(o[j2][2] * inv1, o[j2][3] * inv1);
    }
}

// ---------------------------------------------------------------------------
// kernel_launch
// ---------------------------------------------------------------------------
extern "C" void kernel_launch(void* const* d_in, const int* in_sizes, int n_in,
                              void* d_out, int out_size)
{
    const float* qo        = (const float*)d_in[0];
    const float* kvo       = (const float*)d_in[1];
    const void*  amask     = d_in[2];
    const float* qmask     = (const float*)d_in[3];
    const void*  kvmask    = d_in[4];
    const float* ln_g      = (const float*)d_in[5];
    const float* ln_b      = (const float*)d_in[6];
    const float* Wq        = (const float*)d_in[7];
    const float* Wkv       = (const float*)d_in[8];
    const float* Wout      = (const float*)d_in[9];
    const float* attn_gate = (const float*)d_in[10];
    const float* ff_ln_g   = (const float*)d_in[11];
    const float* ff_ln_b   = (const float*)d_in[12];
    const float* W1        = (const float*)d_in[13];
    const float* W2        = (const float*)d_in[14];
    const float* ff_gate   = (const float*)d_in[15];
    float* out = (float*)d_out;

    float *lnbuf, *qb, *kvb, *aob, *xb, *hb;
    cudaGetSymbolAddress((void**)&lnbuf, g_lnbuf);
    cudaGetSymbolAddress((void**)&qb,    g_q);
    cudaGetSymbolAddress((void**)&kvb,   g_kv);
    cudaGetSymbolAddress((void**)&aob,   g_ao);
    cudaGetSymbolAddress((void**)&xb,    g_x);
    cudaGetSymbolAddress((void**)&hb,    g_h);

    cudaFuncSetAttribute(tf32_gemm_kernel<0>,
        cudaFuncAttributeMaxDynamicSharedMemorySize, GEMM_SMEM);
    cudaFuncSetAttribute(tf32_gemm_kernel<1>,
        cudaFuncAttributeMaxDynamicSharedMemorySize, GEMM_SMEM);
    cudaFuncSetAttribute(tf32_gemm_kernel<2>,
        cudaFuncAttributeMaxDynamicSharedMemorySize, GEMM_SMEM);
    cudaFuncSetAttribute(attn_mma_kernel,
        cudaFuncAttributeMaxDynamicSharedMemorySize, ATTN2_SMEM);

    detect_mask_kernel<<<1, 256>>>((const unsigned int*)amask, 2048);

    const int ROWS = B_ * T1_;   // 8192

    // 1) LN(qo)
    ln_kernel<<<ROWS, 256>>>(qo, ln_g, ln_b, lnbuf);
    // 2) q = LN(qo) @ Wq        (8192 x 512 x 1024)
    tf32_gemm_kernel<0><<<dim3(INNER_ / 128, ROWS / 128), 256, GEMM_SMEM>>>(
        lnbuf, Wq, qb, ROWS, INNER_, DIM_, nullptr, nullptr);
    // 3) kv = kvo_flat @ Wkv    (2048 x 1024 x 1024)
    tf32_gemm_kernel<0><<<dim3((2 * INNER_) / 128, (B_ * JT_) / 128), 256, GEMM_SMEM>>>(
        kvo, Wkv, kvb, B_ * JT_, 2 * INNER_, DIM_, nullptr, nullptr);
    // 4) fused masked mma attention -> g_ao
    attn_mma_kernel<<<dim3(T1_ / 64, H_, B_), 128, ATTN2_SMEM>>>(
        qb, kvb, amask, kvmask, qmask, aob);
    // 5) x = (ao @ Wout) * tanh(attn_gate) + qo   (8192 x 1024 x 512)
    tf32_gemm_kernel<2><<<dim3(DIM_ / 128, ROWS / 128), 256, GEMM_SMEM>>>(
        aob, Wout, xb, ROWS, DIM_, INNER_, attn_gate, qo);
    // 6) LN(x)
    ln_kernel<<<ROWS, 256>>>(xb, ff_ln_g, ff_ln_b, lnbuf);
    // 7) h = gelu(LN(x) @ W1)   (8192 x 4096 x 1024)
    tf32_gemm_kernel<1><<<dim3(DFF_ / 128, ROWS / 128), 256, GEMM_SMEM>>>(
        lnbuf, W1, hb, ROWS, DFF_, DIM_, nullptr, nullptr);
    // 8) out = (h @ W2) * tanh(ff_gate) + x   (8192 x 1024 x 4096)
    tf32_gemm_kernel<2><<<dim3(DIM_ / 128, ROWS / 128), 256, GEMM_SMEM>>>(
        hb, W2, out, ROWS, DIM_, DFF_, ff_gate, xb);
}

// round 6
// speedup vs baseline: 2.7322x; 1.0599x over previous
#include <cuda_runtime.h>
#include <cuda_bf16.h>
#include <math.h>
#include <stdint.h>

// ---------------------------------------------------------------------------
// Problem constants
// ---------------------------------------------------------------------------
#define B_     4
#define T1_    2048
#define JT_    512
#define DIM_   1024
#define INNER_ 512
#define DFF_   4096
#define H_     8
#define DH_    64

// ---------------------------------------------------------------------------
// Scratch (device globals; no allocation allowed)
// ---------------------------------------------------------------------------
__device__ float g_lnbuf[(size_t)B_*T1_*DIM_];
__device__ float g_q   [(size_t)B_*T1_*INNER_];
__device__ float g_kv  [(size_t)B_*JT_*2*INNER_];
__device__ float g_ao  [(size_t)B_*T1_*INNER_];
__device__ float g_x   [(size_t)B_*T1_*DIM_];
__device__ float g_h   [(size_t)B_*T1_*DFF_];
__device__ int   g_mask_mode;

// ---------------------------------------------------------------------------
// Mask dtype detection (bool may arrive as uint8 / int32 / float32)
// ---------------------------------------------------------------------------
__global__ void detect_mask_kernel(const unsigned int* __restrict__ w, int nwords)
{
    __shared__ int f_u8, f_f32;
    if (threadIdx.x == 0) { f_u8 = 0; f_f32 = 0; }
    __syncthreads();
    int u8 = 0, f32 = 0;
    for (int i = threadIdx.x; i < nwords; i += blockDim.x) {
        unsigned int x = w[i];
        if (x == 0x3F800000u)            f32 = 1;
        else if (x != 0u && x != 1u)     u8  = 1;
    }
    if (u8)  atomicOr(&f_u8, 1);
    if (f32) atomicOr(&f_f32, 1);
    __syncthreads();
    if (threadIdx.x == 0)
        g_mask_mode = f_u8 ? 0 : (f_f32 ? 2 : 1);
}

__device__ __forceinline__ bool read_mask(const void* p, size_t i, int mode)
{
    if (mode == 1) return ((const int*)p)[i] != 0;
    if (mode == 2) return ((const float*)p)[i] != 0.0f;
    return ((const unsigned char*)p)[i] != 0;
}

// ---------------------------------------------------------------------------
// LayerNorm over last dim (1024). One block per row, 256 threads.
// ---------------------------------------------------------------------------
__global__ __launch_bounds__(256) void ln_kernel(
    const float* __restrict__ x, const float* __restrict__ gw,
    const float* __restrict__ bw, float* __restrict__ y)
{
    const int row = blockIdx.x;
    const float* xr = x + (size_t)row * DIM_;
    float v[4];
    float s = 0.f, s2 = 0.f;
    #pragma unroll
    for (int k = 0; k < 4; k++) {
        v[k] = xr[threadIdx.x + k * 256];
        s += v[k]; s2 += v[k] * v[k];
    }
    #pragma unroll
    for (int o = 16; o; o >>= 1) {
        s  += __shfl_xor_sync(0xffffffffu, s,  o);
        s2 += __shfl_xor_sync(0xffffffffu, s2, o);
    }
    __shared__ float sh[2][8];
    const int warp = threadIdx.x >> 5, lane = threadIdx.x & 31;
    if (lane == 0) { sh[0][warp] = s; sh[1][warp] = s2; }
    __syncthreads();
    if (threadIdx.x == 0) {
        float S = 0.f, S2 = 0.f;
        #pragma unroll
        for (int w = 0; w < 8; w++) { S += sh[0][w]; S2 += sh[1][w]; }
        const float mu  = S  * (1.0f / DIM_);
        const float var = S2 * (1.0f / DIM_) - mu * mu;
        sh[0][0] = mu;
        sh[1][0] = rsqrtf(var + 1e-5f);
    }
    __syncthreads();
    const float mu = sh[0][0], inv = sh[1][0];
    float* yr = y + (size_t)row * DIM_;
    #pragma unroll
    for (int k = 0; k < 4; k++) {
        const int c = threadIdx.x + k * 256;
        yr[c] = (v[k] - mu) * inv * gw[c] + bw[c];
    }
}

// ---------------------------------------------------------------------------
// TF32 helpers
// ---------------------------------------------------------------------------
__device__ __forceinline__ float tf32r(float x)
{
    uint32_t r;
    asm("cvt.rna.tf32.f32 %0, %1;" : "=r"(r) : "f"(x));
    return __uint_as_float(r);
}

__device__ __forceinline__ void mma_tf32(
    float* c, const uint32_t* a, const uint32_t* b)
{
    asm volatile(
        "mma.sync.aligned.m16n8k8.row.col.f32.tf32.tf32.f32 "
        "{%0,%1,%2,%3},{%4,%5,%6,%7},{%8,%9},{%0,%1,%2,%3};"
        : "+f"(c[0]), "+f"(c[1]), "+f"(c[2]), "+f"(c[3])
        : "r"(a[0]), "r"(a[1]), "r"(a[2]), "r"(a[3]), "r"(b[0]), "r"(b[1]));
}

__device__ __forceinline__ void cpa16(float* dst_smem, const float* src_gmem)
{
    uint32_t d = (uint32_t)__cvta_generic_to_shared(dst_smem);
    asm volatile("cp.async.cg.shared.global [%0], [%1], 16;"
                 :: "r"(d), "l"(src_gmem));
}

// ---------------------------------------------------------------------------
// TF32 tensor-core GEMM v2: cp.async staging (no register staging, no cvt —
// mma.tf32 truncates raw f32 operands), double-buffered, 2 CTAs/SM.
// 128x128x32 tile, 256 threads = 8 warps (4m x 2n), warp tile 32x64.
// EPI: 0 = none, 1 = exact GELU, 2 = v*tanh(*gate) + res[r,c]
// ---------------------------------------------------------------------------
#define G_AP 36
#define G_BP 136
#define G_ASZ (128 * G_AP)
#define G_BSZ (32 * G_BP)
#define GEMM_SMEM ((2 * (G_ASZ + G_BSZ)) * (int)sizeof(float))

template <int EPI>
__global__ __launch_bounds__(256, 2) void tf32_gemm_kernel(
    const float* __restrict__ A, const float* __restrict__ Bm,
    float* __restrict__ C, int M, int N, int K,
    const float* __restrict__ gate, const float* __restrict__ res)
{
    extern __shared__ float smp[];
    float* Abuf[2] = { smp, smp + G_ASZ + G_BSZ };
    float* Bbuf[2] = { smp + G_ASZ, smp + 2 * G_ASZ + G_BSZ };

    const int tid  = threadIdx.x;
    const int warp = tid >> 5, lane = tid & 31;
    const int wm = warp >> 1, wn = warp & 1;
    const int g = lane >> 2, l4 = lane & 3;
    const int row0 = blockIdx.y << 7, col0 = blockIdx.x << 7;

    const int ar = tid >> 3, ac = (tid & 7) << 2;   // A: 128x32, 4 x 16B/thread
    const int br = tid >> 5, bc = (tid & 31) << 2;  // B: 32x128, 4 x 16B/thread
    const float* Ag = A  + (size_t)(row0 + ar) * K + ac;
    const float* Bg = Bm + (size_t)br * N + col0 + bc;

    float c[2][8][4];
    #pragma unroll
    for (int i = 0; i < 2; i++)
        #pragma unroll
        for (int j = 0; j < 8; j++)
            #pragma unroll
            for (int q = 0; q < 4; q++) c[i][j][q] = 0.f;

    const int iters = K >> 5;

    // prologue: async-load tile 0 into buf 0
    #pragma unroll
    for (int i = 0; i < 4; i++)
        cpa16(Abuf[0] + (ar + 32 * i) * G_AP + ac, Ag + (size_t)(32 * i) * K);
    #pragma unroll
    for (int i = 0; i < 4; i++)
        cpa16(Bbuf[0] + (br + 8 * i) * G_BP + bc, Bg + (size_t)(8 * i) * N);
    asm volatile("cp.async.commit_group;");

    for (int t = 0; t < iters; t++) {
        if (t + 1 < iters) {
            const int k1 = (t + 1) << 5;
            float* Ad = Abuf[(t + 1) & 1];
            float* Bd = Bbuf[(t + 1) & 1];
            #pragma unroll
            for (int i = 0; i < 4; i++)
                cpa16(Ad + (ar + 32 * i) * G_AP + ac,
                      Ag + (size_t)(32 * i) * K + k1);
            #pragma unroll
            for (int i = 0; i < 4; i++)
                cpa16(Bd + (br + 8 * i) * G_BP + bc,
                      Bg + (size_t)(k1 + 8 * i) * N);
            asm volatile("cp.async.commit_group;");
            asm volatile("cp.async.wait_group 1;");
        } else {
            asm volatile("cp.async.wait_group 0;");
        }
        __syncthreads();

        const float* As = Abuf[t & 1];
        const float* Bs = Bbuf[t & 1];
        #pragma unroll
        for (int ks = 0; ks < 4; ks++) {
            uint32_t a[2][4], b[8][2];
            #pragma unroll
            for (int i = 0; i < 2; i++) {
                const float* ap = As + (wm * 32 + i * 16 + g) * G_AP + ks * 8 + l4;
                a[i][0] = __float_as_uint(ap[0]);
                a[i][1] = __float_as_uint(ap[8 * G_AP]);
                a[i][2] = __float_as_uint(ap[4]);
                a[i][3] = __float_as_uint(ap[8 * G_AP + 4]);
            }
            const float* bp = Bs + (ks * 8 + l4) * G_BP + wn * 64 + g;
            #pragma unroll
            for (int j = 0; j < 8; j++) {
                b[j][0] = __float_as_uint(bp[j * 8]);
                b[j][1] = __float_as_uint(bp[4 * G_BP + j * 8]);
            }
            #pragma unroll
            for (int i = 0; i < 2; i++)
                #pragma unroll
                for (int j = 0; j < 8; j++)
                    mma_tf32(c[i][j], a[i], b[j]);
        }
        __syncthreads();   // compute done before buf[t&1] is re-filled at t+2
    }

    float gt = 0.f;
    if (EPI == 2) gt = tanhf(gate[0]);
    #pragma unroll
    for (int i = 0; i < 2; i++) {
        const int r_lo = row0 + wm * 32 + i * 16 + g;
        #pragma unroll
        for (int j = 0; j < 8; j++) {
            const int cc = col0 + wn * 64 + j * 8 + 2 * l4;
            #pragma unroll
            for (int half = 0; half < 2; half++) {
                const size_t rr = (size_t)(r_lo + 8 * half);
                float v0 = c[i][j][2 * half + 0];
                float v1 = c[i][j][2 * half + 1];
                if (EPI == 1) {
                    v0 = 0.5f * v0 * (1.0f + erff(v0 * 0.70710678118654752f));
                    v1 = 0.5f * v1 * (1.0f + erff(v1 * 0.70710678118654752f));
                }
                if (EPI == 2) {
                    const float2 rv =
                        *reinterpret_cast<const float2*>(res + rr * N + cc);
                    v0 = v0 * gt + rv.x;
                    v1 = v1 * gt + rv.y;
                }
                *reinterpret_cast<float2*>(C + rr * N + cc) = make_float2(v0, v1);
            }
        }
    }
}

// ---------------------------------------------------------------------------
// mma-based fused masked flash attention (unchanged from R4, validated).
// ---------------------------------------------------------------------------
#define AT_PAD  68
#define KEEP_P  132
#define AT_QS   (64 * AT_PAD)
#define AT_KS   (128 * AT_PAD)
#define AT_VS   (128 * AT_PAD)
#define ATTN2_SMEM (((AT_QS + AT_KS + AT_VS) * 4) + 64 * KEEP_P)

__global__ __launch_bounds__(128) void attn_mma_kernel(
    const float* __restrict__ Q,
    const float* __restrict__ KV,
    const void*  __restrict__ amask,
    const void*  __restrict__ kvmask,
    const float* __restrict__ qmask,
    float* __restrict__ AO)
{
    extern __shared__ float sm[];
    float* Qs = sm;
    float* Ks = Qs + AT_QS;
    float* Vs = Ks + AT_KS;
    unsigned char* keep = (unsigned char*)(Vs + AT_VS);

    const int i0 = blockIdx.x * 64;
    const int h  = blockIdx.y;
    const int b  = blockIdx.z;
    const int tid  = threadIdx.x;
    const int warp = tid >> 5, lane = tid & 31;
    const int g = lane >> 2, q4 = lane & 3;
    const int mode = g_mask_mode;
    const int row_g = warp * 16 + g;

    for (int t = tid; t < 64 * 16; t += 128) {
        const int rr = t >> 4, c4 = (t & 15) << 2;
        const float4 v = *reinterpret_cast<const float4*>(
            Q + ((size_t)(b * T1_ + i0 + rr)) * INNER_ + h * DH_ + c4);
        float* d = Qs + rr * AT_PAD + c4;
        d[0] = v.x * 0.125f; d[1] = v.y * 0.125f;
        d[2] = v.z * 0.125f; d[3] = v.w * 0.125f;
    }

    float m0 = -1e38f, m1 = -1e38f, l0 = 0.f, l1 = 0.f;
    float o[8][4];
    #pragma unroll
    for (int j = 0; j < 8; j++)
        #pragma unroll
        for (int q = 0; q < 4; q++) o[j][q] = 0.f;

    for (int kt = 0; kt < 4; kt++) {
        __syncthreads();

        for (int t = tid; t < 128 * 16; t += 128) {
            const int rr = t >> 4, c4 = (t & 15) << 2;
            const float* kp = KV + ((size_t)(b * JT_ + kt * 128 + rr)) * (2 * INNER_)
                                 + h * DH_ + c4;
            const float4 k4 = *reinterpret_cast<const float4*>(kp);
            const float4 v4 = *reinterpret_cast<const float4*>(kp + INNER_);
            float* kd = Ks + rr * AT_PAD + c4;
            kd[0] = tf32r(k4.x); kd[1] = tf32r(k4.y);
            kd[2] = tf32r(k4.z); kd[3] = tf32r(k4.w);
            float* vd = Vs + rr * AT_PAD + c4;
            vd[0] = tf32r(v4.x); vd[1] = tf32r(v4.y);
            vd[2] = tf32r(v4.z); vd[3] = tf32r(v4.w);
        }
        for (int t = tid; t < 64 * 128; t += 128) {
            const int rr = t >> 7, cc = t & 127;
            const bool a = read_mask(amask,
                ((size_t)(b * T1_ + i0 + rr)) * JT_ + kt * 128 + cc, mode);
            const bool k = read_mask(kvmask, (size_t)b * JT_ + kt * 128 + cc, mode);
            keep[rr * KEEP_P + cc] = (a && k) ? 1 : 0;
        }
        __syncthreads();

        uint32_t qa[8][4];
        #pragma unroll
        for (int ks = 0; ks < 8; ks++) {
            const float* base = Qs + (warp * 16) * AT_PAD + ks * 8 + q4;
            qa[ks][0] = __float_as_uint(tf32r(base[g * AT_PAD]));
            qa[ks][1] = __float_as_uint(tf32r(base[(g + 8) * AT_PAD]));
            qa[ks][2] = __float_as_uint(tf32r(base[g * AT_PAD + 4]));
            qa[ks][3] = __float_as_uint(tf32r(base[(g + 8) * AT_PAD + 4]));
        }

        float sfr[16][4];
        #pragma unroll
        for (int j = 0; j < 16; j++)
            #pragma unroll
            for (int q = 0; q < 4; q++) sfr[j][q] = 0.f;
        #pragma unroll
        for (int ks = 0; ks < 8; ks++) {
            #pragma unroll
            for (int j = 0; j < 16; j++) {
                uint32_t bb[2];
                const float* kp = Ks + (j * 8 + g) * AT_PAD + ks * 8 + q4;
                bb[0] = __float_as_uint(kp[0]);
                bb[1] = __float_as_uint(kp[4]);
                mma_tf32(sfr[j], qa[ks], bb);
            }
        }

        const unsigned char* kr0 = keep + row_g * KEEP_P;
        const unsigned char* kr1 = kr0 + 8 * KEEP_P;
        float mt0 = -1e30f, mt1 = -1e30f;
        #pragma unroll
        for (int j = 0; j < 16; j++) {
            const int c0 = j * 8 + 2 * q4;
            sfr[j][0] = kr0[c0]     ? sfr[j][0] : -1e30f;
            sfr[j][1] = kr0[c0 + 1] ? sfr[j][1] : -1e30f;
            sfr[j][2] = kr1[c0]     ? sfr[j][2] : -1e30f;
            sfr[j][3] = kr1[c0 + 1] ? sfr[j][3] : -1e30f;
            mt0 = fmaxf(mt0, fmaxf(sfr[j][0], sfr[j][1]));
            mt1 = fmaxf(mt1, fmaxf(sfr[j][2], sfr[j][3]));
        }
        mt0 = fmaxf(mt0, __shfl_xor_sync(0xffffffffu, mt0, 1));
        mt0 = fmaxf(mt0, __shfl_xor_sync(0xffffffffu, mt0, 2));
        mt1 = fmaxf(mt1, __shfl_xor_sync(0xffffffffu, mt1, 1));
        mt1 = fmaxf(mt1, __shfl_xor_sync(0xffffffffu, mt1, 2));

        const float mn0 = fmaxf(m0, mt0), mn1 = fmaxf(m1, mt1);
        const float al0 = (m0 > -1e37f) ? __expf(m0 - mn0) : 0.f;
        const float al1 = (m1 > -1e37f) ? __expf(m1 - mn1) : 0.f;

        float ps0 = 0.f, ps1 = 0.f;
        #pragma unroll
        for (int j = 0; j < 16; j++) {
            float p0 = (sfr[j][0] > -1e29f) ? __expf(sfr[j][0] - mn0) : 0.f;
            float p1 = (sfr[j][1] > -1e29f) ? __expf(sfr[j][1] - mn0) : 0.f;
            float p2 = (sfr[j][2] > -1e29f) ? __expf(sfr[j][2] - mn1) : 0.f;
            float p3 = (sfr[j][3] > -1e29f) ? __expf(sfr[j][3] - mn1) : 0.f;
            ps0 += p0 + p1; ps1 += p2 + p3;
            sfr[j][0] = tf32r(p0); sfr[j][1] = tf32r(p1);
            sfr[j][2] = tf32r(p2); sfr[j][3] = tf32r(p3);
        }
        ps0 += __shfl_xor_sync(0xffffffffu, ps0, 1);
        ps0 += __shfl_xor_sync(0xffffffffu, ps0, 2);
        ps1 += __shfl_xor_sync(0xffffffffu, ps1, 1);
        ps1 += __shfl_xor_sync(0xffffffffu, ps1, 2);
        l0 = l0 * al0 + ps0;
        l1 = l1 * al1 + ps1;
        m0 = mn0; m1 = mn1;

        #pragma unroll
        for (int j = 0; j < 8; j++) {
            o[j][0] *= al0; o[j][1] *= al0;
            o[j][2] *= al1; o[j][3] *= al1;
        }

        const int srcA = (lane & ~3) | (q4 >> 1);
        const int srcB = srcA + 2;
        const bool odd = (q4 & 1);
        #pragma unroll
        for (int ks = 0; ks < 16; ks++) {
            const float v0a = __shfl_sync(0xffffffffu, sfr[ks][0], srcA);
            const float v1a = __shfl_sync(0xffffffffu, sfr[ks][1], srcA);
            const float v0b = __shfl_sync(0xffffffffu, sfr[ks][0], srcB);
            const float v1b = __shfl_sync(0xffffffffu, sfr[ks][1], srcB);
            const float w0a = __shfl_sync(0xffffffffu, sfr[ks][2], srcA);
            const float w1a = __shfl_sync(0xffffffffu, sfr[ks][3], srcA);
            const float w0b = __shfl_sync(0xffffffffu, sfr[ks][2], srcB);
            const float w1b = __shfl_sync(0xffffffffu, sfr[ks][3], srcB);
            uint32_t a[4];
            a[0] = __float_as_uint(odd ? v1a : v0a);
            a[1] = __float_as_uint(odd ? w1a : w0a);
            a[2] = __float_as_uint(odd ? v1b : v0b);
            a[3] = __float_as_uint(odd ? w1b : w0b);
            const float* vb = Vs + (ks * 8 + q4) * AT_PAD;
            #pragma unroll
            for (int j2 = 0; j2 < 8; j2++) {
                uint32_t bb[2];
                bb[0] = __float_as_uint(vb[j2 * 8 + g]);
                bb[1] = __float_as_uint(vb[4 * AT_PAD + j2 * 8 + g]);
                mma_tf32(o[j2], a, bb);
            }
        }
    }

    const float qm0 = qmask[b * T1_ + i0 + row_g];
    const float qm1 = qmask[b * T1_ + i0 + row_g + 8];
    const float inv0 = (l0 > 0.f) ? qm0 / l0 : 0.f;
    const float inv1 = (l1 > 0.f) ? qm1 / l1 : 0.f;
    float* dst0 = AO + ((size_t)(b * T1_ + i0 + row_g)) * INNER_ + h * DH_;
    float* dst1 = dst0 + (size_t)8 * INNER_;
    #pragma unroll
    for (int j2 = 0; j2 < 8; j2++) {
        const int cc = j2 * 8 + 2 * q4;
        *reinterpret_cast<float2*>(dst0 + cc) =
            make_float2(o[j2][0] * inv0, o[j2][1] * inv0);
        *reinterpret_cast<float2*>(dst1 + cc) =
            make_float2(o[j2][2] * inv1, o[j2][3] * inv1);
    }
}

// ---------------------------------------------------------------------------
// kernel_launch
// ---------------------------------------------------------------------------
extern "C" void kernel_launch(void* const* d_in, const int* in_sizes, int n_in,
                              void* d_out, int out_size)
{
    const float* qo        = (const float*)d_in[0];
    const float* kvo       = (const float*)d_in[1];
    const void*  amask     = d_in[2];
    const float* qmask     = (const float*)d_in[3];
    const void*  kvmask    = d_in[4];
    const float* ln_g      = (const float*)d_in[5];
    const float* ln_b      = (const float*)d_in[6];
    const float* Wq        = (const float*)d_in[7];
    const float* Wkv       = (const float*)d_in[8];
    const float* Wout      = (const float*)d_in[9];
    const float* attn_gate = (const float*)d_in[10];
    const float* ff_ln_g   = (const float*)d_in[11];
    const float* ff_ln_b   = (const float*)d_in[12];
    const float* W1        = (const float*)d_in[13];
    const float* W2        = (const float*)d_in[14];
    const float* ff_gate   = (const float*)d_in[15];
    float* out = (float*)d_out;

    float *lnbuf, *qb, *kvb, *aob, *xb, *hb;
    cudaGetSymbolAddress((void**)&lnbuf, g_lnbuf);
    cudaGetSymbolAddress((void**)&qb,    g_q);
    cudaGetSymbolAddress((void**)&kvb,   g_kv);
    cudaGetSymbolAddress((void**)&aob,   g_ao);
    cudaGetSymbolAddress((void**)&xb,    g_x);
    cudaGetSymbolAddress((void**)&hb,    g_h);

    cudaFuncSetAttribute(tf32_gemm_kernel<0>,
        cudaFuncAttributeMaxDynamicSharedMemorySize, GEMM_SMEM);
    cudaFuncSetAttribute(tf32_gemm_kernel<1>,
        cudaFuncAttributeMaxDynamicSharedMemorySize, GEMM_SMEM);
    cudaFuncSetAttribute(tf32_gemm_kernel<2>,
        cudaFuncAttributeMaxDynamicSharedMemorySize, GEMM_SMEM);
    cudaFuncSetAttribute(attn_mma_kernel,
        cudaFuncAttributeMaxDynamicSharedMemorySize, ATTN2_SMEM);

    detect_mask_kernel<<<1, 256>>>((const unsigned int*)amask, 2048);

    const int ROWS = B_ * T1_;   // 8192

    // 1) LN(qo)
    ln_kernel<<<ROWS, 256>>>(qo, ln_g, ln_b, lnbuf);
    // 2) q = LN(qo) @ Wq        (8192 x 512 x 1024)
    tf32_gemm_kernel<0><<<dim3(INNER_ / 128, ROWS / 128), 256, GEMM_SMEM>>>(
        lnbuf, Wq, qb, ROWS, INNER_, DIM_, nullptr, nullptr);
    // 3) kv = kvo_flat @ Wkv    (2048 x 1024 x 1024)
    tf32_gemm_kernel<0><<<dim3((2 * INNER_) / 128, (B_ * JT_) / 128), 256, GEMM_SMEM>>>(
        kvo, Wkv, kvb, B_ * JT_, 2 * INNER_, DIM_, nullptr, nullptr);
    // 4) fused masked mma attention -> g_ao
    attn_mma_kernel<<<dim3(T1_ / 64, H_, B_), 128, ATTN2_SMEM>>>(
        qb, kvb, amask, kvmask, qmask, aob);
    // 5) x = (ao @ Wout) * tanh(attn_gate) + qo   (8192 x 1024 x 512)
    tf32_gemm_kernel<2><<<dim3(DIM_ / 128, ROWS / 128), 256, GEMM_SMEM>>>(
        aob, Wout, xb, ROWS, DIM_, INNER_, attn_gate, qo);
    // 6) LN(x)
    ln_kernel<<<ROWS, 256>>>(xb, ff_ln_g, ff_ln_b, lnbuf);
    // 7) h = gelu(LN(x) @ W1)   (8192 x 4096 x 1024)
    tf32_gemm_kernel<1><<<dim3(DFF_ / 128, ROWS / 128), 256, GEMM_SMEM>>>(
        lnbuf, W1, hb, ROWS, DFF_, DIM_, nullptr, nullptr);
    // 8) out = (h @ W2) * tanh(ff_gate) + x   (8192 x 1024 x 4096)
    tf32_gemm_kernel<2><<<dim3(DIM_ / 128, ROWS / 128), 256, GEMM_SMEM>>>(
        hb, W2, out, ROWS, DIM_, DFF_, ff_gate, xb);
}

// round 7
// speedup vs baseline: 3.5196x; 1.2882x over previous
#include <cuda_runtime.h>
#include <cuda_bf16.h>
#include <math.h>
#include <stdint.h>

// ---------------------------------------------------------------------------
// Problem constants
// ---------------------------------------------------------------------------
#define B_     4
#define T1_    2048
#define JT_    512
#define DIM_   1024
#define INNER_ 512
#define DFF_   4096
#define H_     8
#define DH_    64

// ---------------------------------------------------------------------------
// Scratch (device globals; no allocation allowed)
// ---------------------------------------------------------------------------
__device__ float g_q [(size_t)B_*T1_*INNER_];        // q projection (f32, attn input)
__device__ float g_kv[(size_t)B_*JT_*2*INNER_];      // k|v projection (f32, attn input)
__device__ float g_x [(size_t)B_*T1_*DIM_];          // attn residual (f32)
__device__ __nv_bfloat16 g_ln_h [(size_t)B_*T1_*DIM_];   // LN output (bf16 GEMM A)
__device__ __nv_bfloat16 g_ao_h [(size_t)B_*T1_*INNER_]; // attn output (bf16 GEMM A)
__device__ __nv_bfloat16 g_h_h  [(size_t)B_*T1_*DFF_];   // gelu output (bf16 GEMM A)
__device__ __nv_bfloat16 g_kvo_h[(size_t)B_*JT_*DIM_];   // kvo in bf16
__device__ __nv_bfloat16 g_wq_t [(size_t)INNER_*DIM_];     // weights, [N][K] bf16
__device__ __nv_bfloat16 g_wkv_t[(size_t)2*INNER_*DIM_];
__device__ __nv_bfloat16 g_wout_t[(size_t)DIM_*INNER_];
__device__ __nv_bfloat16 g_w1_t [(size_t)DFF_*DIM_];
__device__ __nv_bfloat16 g_w2_t [(size_t)DIM_*DFF_];
__device__ int g_mask_mode;

// ---------------------------------------------------------------------------
// Mask dtype detection (bool may arrive as uint8 / int32 / float32)
// ---------------------------------------------------------------------------
__global__ void detect_mask_kernel(const unsigned int* __restrict__ w, int nwords)
{
    __shared__ int f_u8, f_f32;
    if (threadIdx.x == 0) { f_u8 = 0; f_f32 = 0; }
    __syncthreads();
    int u8 = 0, f32 = 0;
    for (int i = threadIdx.x; i < nwords; i += blockDim.x) {
        unsigned int x = w[i];
        if (x == 0x3F800000u)            f32 = 1;
        else if (x != 0u && x != 1u)     u8  = 1;
    }
    if (u8)  atomicOr(&f_u8, 1);
    if (f32) atomicOr(&f_f32, 1);
    __syncthreads();
    if (threadIdx.x == 0)
        g_mask_mode = f_u8 ? 0 : (f_f32 ? 2 : 1);
}

__device__ __forceinline__ bool read_mask(const void* p, size_t i, int mode)
{
    if (mode == 1) return ((const int*)p)[i] != 0;
    if (mode == 2) return ((const float*)p)[i] != 0.0f;
    return ((const unsigned char*)p)[i] != 0;
}

// ---------------------------------------------------------------------------
// Conversion pre-kernels
// ---------------------------------------------------------------------------
__global__ __launch_bounds__(256) void f32_to_bf16_kernel(
    const float* __restrict__ in, __nv_bfloat16* __restrict__ out, int n4)
{
    const int i = blockIdx.x * 256 + threadIdx.x;
    if (i < n4) {
        const float4 v = reinterpret_cast<const float4*>(in)[i];
        __nv_bfloat162* o = reinterpret_cast<__nv_bfloat162*>(out) + i * 2;
        o[0] = __floats2bfloat162_rn(v.x, v.y);
        o[1] = __floats2bfloat162_rn(v.z, v.w);
    }
}

// in: f32 [K][N]  ->  out: bf16 [N][K]
__global__ __launch_bounds__(256) void transpose_bf16_kernel(
    const float* __restrict__ in, __nv_bfloat16* __restrict__ out, int K, int N)
{
    __shared__ float tile[32][33];
    const int n0 = blockIdx.x * 32, k0 = blockIdx.y * 32;
    const int tx = threadIdx.x, ty = threadIdx.y;
    #pragma unroll
    for (int r = ty; r < 32; r += 8)
        tile[r][tx] = in[(size_t)(k0 + r) * N + n0 + tx];
    __syncthreads();
    #pragma unroll
    for (int r = ty; r < 32; r += 8)
        out[(size_t)(n0 + r) * K + k0 + tx] = __float2bfloat16(tile[tx][r]);
}

// ---------------------------------------------------------------------------
// LayerNorm over last dim (1024). One block per row, 256 threads. bf16 out.
// ---------------------------------------------------------------------------
__global__ __launch_bounds__(256) void ln_kernel(
    const float* __restrict__ x, const float* __restrict__ gw,
    const float* __restrict__ bw, __nv_bfloat16* __restrict__ y)
{
    const int row = blockIdx.x;
    const float* xr = x + (size_t)row * DIM_;
    float v[4];
    float s = 0.f, s2 = 0.f;
    #pragma unroll
    for (int k = 0; k < 4; k++) {
        v[k] = xr[threadIdx.x + k * 256];
        s += v[k]; s2 += v[k] * v[k];
    }
    #pragma unroll
    for (int o = 16; o; o >>= 1) {
        s  += __shfl_xor_sync(0xffffffffu, s,  o);
        s2 += __shfl_xor_sync(0xffffffffu, s2, o);
    }
    __shared__ float sh[2][8];
    const int warp = threadIdx.x >> 5, lane = threadIdx.x & 31;
    if (lane == 0) { sh[0][warp] = s; sh[1][warp] = s2; }
    __syncthreads();
    if (threadIdx.x == 0) {
        float S = 0.f, S2 = 0.f;
        #pragma unroll
        for (int w = 0; w < 8; w++) { S += sh[0][w]; S2 += sh[1][w]; }
        const float mu  = S  * (1.0f / DIM_);
        const float var = S2 * (1.0f / DIM_) - mu * mu;
        sh[0][0] = mu;
        sh[1][0] = rsqrtf(var + 1e-5f);
    }
    __syncthreads();
    const float mu = sh[0][0], inv = sh[1][0];
    __nv_bfloat16* yr = y + (size_t)row * DIM_;
    #pragma unroll
    for (int k = 0; k < 4; k++) {
        const int c = threadIdx.x + k * 256;
        yr[c] = __float2bfloat16((v[k] - mu) * inv * gw[c] + bw[c]);
    }
}

// ---------------------------------------------------------------------------
// helpers
// ---------------------------------------------------------------------------
__device__ __forceinline__ float tf32r(float x)
{
    uint32_t r;
    asm("cvt.rna.tf32.f32 %0, %1;" : "=r"(r) : "f"(x));
    return __uint_as_float(r);
}

__device__ __forceinline__ void mma_tf32(
    float* c, const uint32_t* a, const uint32_t* b)
{
    asm volatile(
        "mma.sync.aligned.m16n8k8.row.col.f32.tf32.tf32.f32 "
        "{%0,%1,%2,%3},{%4,%5,%6,%7},{%8,%9},{%0,%1,%2,%3};"
        : "+f"(c[0]), "+f"(c[1]), "+f"(c[2]), "+f"(c[3])
        : "r"(a[0]), "r"(a[1]), "r"(a[2]), "r"(a[3]), "r"(b[0]), "r"(b[1]));
}

__device__ __forceinline__ void mma_bf16(
    float* c, const uint32_t* a, const uint32_t* b)
{
    asm volatile(
        "mma.sync.aligned.m16n8k16.row.col.f32.bf16.bf16.f32 "
        "{%0,%1,%2,%3},{%4,%5,%6,%7},{%8,%9},{%0,%1,%2,%3};"
        : "+f"(c[0]), "+f"(c[1]), "+f"(c[2]), "+f"(c[3])
        : "r"(a[0]), "r"(a[1]), "r"(a[2]), "r"(a[3]), "r"(b[0]), "r"(b[1]));
}

__device__ __forceinline__ void cpa16(void* dst_smem, const void* src_gmem)
{
    uint32_t d = (uint32_t)__cvta_generic_to_shared(dst_smem);
    asm volatile("cp.async.cg.shared.global [%0], [%1], 16;"
                 :: "r"(d), "l"(src_gmem));
}

// ---------------------------------------------------------------------------
// bf16 tensor-core GEMM: C[M,N] = epi(A[M,K] @ Bt[N,K]^T)
// A: bf16 [M][K] row-major.  Bt: bf16 [N][K] (weights pre-transposed).
// 128x128x32 tile, 256 threads = 8 warps (4m x 2n), warp tile 32x64 via
// m16n8k16. Both smem tiles are 128 rows x 32 cols bf16 at pitch 40 (80 B),
// staged by cp.async; fragment LDS.32 pattern is bank-conflict-free
// (word = 20g + q4 mod 32, distinct over the warp).
// EPI: 0 none, 1 exact GELU, 2 v*tanh(*gate)+res. OBF: bf16 C output.
// ---------------------------------------------------------------------------
#define P_SM 40
#define TILE_B (128 * P_SM)                 // bf16 elems per tile
#define GEMM_SMEM (4 * TILE_B * (int)sizeof(__nv_bfloat16))   // 40960 B

template <int EPI, int OBF>
__global__ __launch_bounds__(256, 2) void bf16_gemm_kernel(
    const __nv_bfloat16* __restrict__ A, const __nv_bfloat16* __restrict__ Bt,
    void* __restrict__ Cv, int M, int N, int K,
    const float* __restrict__ gate, const float* __restrict__ res)
{
    extern __shared__ __nv_bfloat16 smh[];
    __nv_bfloat16* Abuf[2] = { smh,              smh + 2 * TILE_B };
    __nv_bfloat16* Bbuf[2] = { smh + TILE_B,     smh + 3 * TILE_B };

    const int tid  = threadIdx.x;
    const int warp = tid >> 5, lane = tid & 31;
    const int wm = warp >> 1, wn = warp & 1;
    const int g = lane >> 2, q4 = lane & 3;
    const int row0 = blockIdx.y << 7, col0 = blockIdx.x << 7;

    // staging: each thread copies 2 x 16B chunks of one 64B row
    const int sr = tid >> 1;             // tile row 0..127
    const int sc = (tid & 1) << 1;       // chunk base 0 or 2
    const __nv_bfloat16* Ag = A  + (size_t)(row0 + sr) * K + sc * 8;
    const __nv_bfloat16* Bg = Bt + (size_t)(col0 + sr) * K + sc * 8;
    __nv_bfloat16* Asd = (__nv_bfloat16*)0;

    float c[2][8][4];
    #pragma unroll
    for (int i = 0; i < 2; i++)
        #pragma unroll
        for (int j = 0; j < 8; j++)
            #pragma unroll
            for (int q = 0; q < 4; q++) c[i][j][q] = 0.f;

    const int iters = K >> 5;

    // prologue
    cpa16(Abuf[0] + sr * P_SM + sc * 8,     Ag);
    cpa16(Abuf[0] + sr * P_SM + sc * 8 + 8, Ag + 8);
    cpa16(Bbuf[0] + sr * P_SM + sc * 8,     Bg);
    cpa16(Bbuf[0] + sr * P_SM + sc * 8 + 8, Bg + 8);
    asm volatile("cp.async.commit_group;");

    for (int t = 0; t < iters; t++) {
        if (t + 1 < iters) {
            const int k1 = (t + 1) << 5;
            __nv_bfloat16* Ad = Abuf[(t + 1) & 1];
            __nv_bfloat16* Bd = Bbuf[(t + 1) & 1];
            cpa16(Ad + sr * P_SM + sc * 8,     Ag + k1);
            cpa16(Ad + sr * P_SM + sc * 8 + 8, Ag + k1 + 8);
            cpa16(Bd + sr * P_SM + sc * 8,     Bg + k1);
            cpa16(Bd + sr * P_SM + sc * 8 + 8, Bg + k1 + 8);
            asm volatile("cp.async.commit_group;");
            asm volatile("cp.async.wait_group 1;");
        } else {
            asm volatile("cp.async.wait_group 0;");
        }
        __syncthreads();

        const __nv_bfloat16* As = Abuf[t & 1];
        const __nv_bfloat16* Bs = Bbuf[t & 1];
        #pragma unroll
        for (int ks = 0; ks < 2; ks++) {
            uint32_t a[2][4], b[8][2];
            #pragma unroll
            for (int i = 0; i < 2; i++) {
                const __nv_bfloat16* ap =
                    As + (wm * 32 + i * 16 + g) * P_SM + ks * 16 + 2 * q4;
                a[i][0] = *reinterpret_cast<const uint32_t*>(ap);
                a[i][1] = *reinterpret_cast<const uint32_t*>(ap + 8 * P_SM);
                a[i][2] = *reinterpret_cast<const uint32_t*>(ap + 8);
                a[i][3] = *reinterpret_cast<const uint32_t*>(ap + 8 * P_SM + 8);
            }
            const __nv_bfloat16* bp =
                Bs + (wn * 64 + g) * P_SM + ks * 16 + 2 * q4;
            #pragma unroll
            for (int j = 0; j < 8; j++) {
                b[j][0] = *reinterpret_cast<const uint32_t*>(bp + j * 8 * P_SM);
                b[j][1] = *reinterpret_cast<const uint32_t*>(bp + j * 8 * P_SM + 8);
            }
            #pragma unroll
            for (int i = 0; i < 2; i++)
                #pragma unroll
                for (int j = 0; j < 8; j++)
                    mma_bf16(c[i][j], a[i], b[j]);
        }
        __syncthreads();
    }

    float gt = 0.f;
    if (EPI == 2) gt = tanhf(gate[0]);
    #pragma unroll
    for (int i = 0; i < 2; i++) {
        const int r_lo = row0 + wm * 32 + i * 16 + g;
        #pragma unroll
        for (int j = 0; j < 8; j++) {
            const int cc = col0 + wn * 64 + j * 8 + 2 * q4;
            #pragma unroll
            for (int half = 0; half < 2; half++) {
                const size_t rr = (size_t)(r_lo + 8 * half);
                float v0 = c[i][j][2 * half + 0];
                float v1 = c[i][j][2 * half + 1];
                if (EPI == 1) {
                    v0 = 0.5f * v0 * (1.0f + erff(v0 * 0.70710678118654752f));
                    v1 = 0.5f * v1 * (1.0f + erff(v1 * 0.70710678118654752f));
                }
                if (EPI == 2) {
                    const float2 rv =
                        *reinterpret_cast<const float2*>(res + rr * N + cc);
                    v0 = v0 * gt + rv.x;
                    v1 = v1 * gt + rv.y;
                }
                if (OBF) {
                    *reinterpret_cast<__nv_bfloat162*>(
                        (__nv_bfloat16*)Cv + rr * N + cc) =
                        __floats2bfloat162_rn(v0, v1);
                } else {
                    *reinterpret_cast<float2*>((float*)Cv + rr * N + cc) =
                        make_float2(v0, v1);
                }
            }
        }
    }
    (void)Asd;
}

// ---------------------------------------------------------------------------
// mma-based fused masked flash attention (validated R4/R6); output now bf16.
// ---------------------------------------------------------------------------
#define AT_PAD  68
#define KEEP_P  132
#define AT_QS   (64 * AT_PAD)
#define AT_KS   (128 * AT_PAD)
#define AT_VS   (128 * AT_PAD)
#define ATTN2_SMEM (((AT_QS + AT_KS + AT_VS) * 4) + 64 * KEEP_P)

__global__ __launch_bounds__(128) void attn_mma_kernel(
    const float* __restrict__ Q,
    const float* __restrict__ KV,
    const void*  __restrict__ amask,
    const void*  __restrict__ kvmask,
    const float* __restrict__ qmask,
    __nv_bfloat16* __restrict__ AO)
{
    extern __shared__ float sm[];
    float* Qs = sm;
    float* Ks = Qs + AT_QS;
    float* Vs = Ks + AT_KS;
    unsigned char* keep = (unsigned char*)(Vs + AT_VS);

    const int i0 = blockIdx.x * 64;
    const int h  = blockIdx.y;
    const int b  = blockIdx.z;
    const int tid  = threadIdx.x;
    const int warp = tid >> 5, lane = tid & 31;
    const int g = lane >> 2, q4 = lane & 3;
    const int mode = g_mask_mode;
    const int row_g = warp * 16 + g;

    for (int t = tid; t < 64 * 16; t += 128) {
        const int rr = t >> 4, c4 = (t & 15) << 2;
        const float4 v = *reinterpret_cast<const float4*>(
            Q + ((size_t)(b * T1_ + i0 + rr)) * INNER_ + h * DH_ + c4);
        float* d = Qs + rr * AT_PAD + c4;
        d[0] = v.x * 0.125f; d[1] = v.y * 0.125f;
        d[2] = v.z * 0.125f; d[3] = v.w * 0.125f;
    }

    float m0 = -1e38f, m1 = -1e38f, l0 = 0.f, l1 = 0.f;
    float o[8][4];
    #pragma unroll
    for (int j = 0; j < 8; j++)
        #pragma unroll
        for (int q = 0; q < 4; q++) o[j][q] = 0.f;

    for (int kt = 0; kt < 4; kt++) {
        __syncthreads();

        for (int t = tid; t < 128 * 16; t += 128) {
            const int rr = t >> 4, c4 = (t & 15) << 2;
            const float* kp = KV + ((size_t)(b * JT_ + kt * 128 + rr)) * (2 * INNER_)
                                 + h * DH_ + c4;
            const float4 k4 = *reinterpret_cast<const float4*>(kp);
            const float4 v4 = *reinterpret_cast<const float4*>(kp + INNER_);
            float* kd = Ks + rr * AT_PAD + c4;
            kd[0] = tf32r(k4.x); kd[1] = tf32r(k4.y);
            kd[2] = tf32r(k4.z); kd[3] = tf32r(k4.w);
            float* vd = Vs + rr * AT_PAD + c4;
            vd[0] = tf32r(v4.x); vd[1] = tf32r(v4.y);
            vd[2] = tf32r(v4.z); vd[3] = tf32r(v4.w);
        }
        for (int t = tid; t < 64 * 128; t += 128) {
            const int rr = t >> 7, cc = t & 127;
            const bool a = read_mask(amask,
                ((size_t)(b * T1_ + i0 + rr)) * JT_ + kt * 128 + cc, mode);
            const bool k = read_mask(kvmask, (size_t)b * JT_ + kt * 128 + cc, mode);
            keep[rr * KEEP_P + cc] = (a && k) ? 1 : 0;
        }
        __syncthreads();

        uint32_t qa[8][4];
        #pragma unroll
        for (int ks = 0; ks < 8; ks++) {
            const float* base = Qs + (warp * 16) * AT_PAD + ks * 8 + q4;
            qa[ks][0] = __float_as_uint(tf32r(base[g * AT_PAD]));
            qa[ks][1] = __float_as_uint(tf32r(base[(g + 8) * AT_PAD]));
            qa[ks][2] = __float_as_uint(tf32r(base[g * AT_PAD + 4]));
            qa[ks][3] = __float_as_uint(tf32r(base[(g + 8) * AT_PAD + 4]));
        }

        float sfr[16][4];
        #pragma unroll
        for (int j = 0; j < 16; j++)
            #pragma unroll
            for (int q = 0; q < 4; q++) sfr[j][q] = 0.f;
        #pragma unroll
        for (int ks = 0; ks < 8; ks++) {
            #pragma unroll
            for (int j = 0; j < 16; j++) {
                uint32_t bb[2];
                const float* kp = Ks + (j * 8 + g) * AT_PAD + ks * 8 + q4;
                bb[0] = __float_as_uint(kp[0]);
                bb[1] = __float_as_uint(kp[4]);
                mma_tf32(sfr[j], qa[ks], bb);
            }
        }

        const unsigned char* kr0 = keep + row_g * KEEP_P;
        const unsigned char* kr1 = kr0 + 8 * KEEP_P;
        float mt0 = -1e30f, mt1 = -1e30f;
        #pragma unroll
        for (int j = 0; j < 16; j++) {
            const int c0 = j * 8 + 2 * q4;
            sfr[j][0] = kr0[c0]     ? sfr[j][0] : -1e30f;
            sfr[j][1] = kr0[c0 + 1] ? sfr[j][1] : -1e30f;
            sfr[j][2] = kr1[c0]     ? sfr[j][2] : -1e30f;
            sfr[j][3] = kr1[c0 + 1] ? sfr[j][3] : -1e30f;
            mt0 = fmaxf(mt0, fmaxf(sfr[j][0], sfr[j][1]));
            mt1 = fmaxf(mt1, fmaxf(sfr[j][2], sfr[j][3]));
        }
        mt0 = fmaxf(mt0, __shfl_xor_sync(0xffffffffu, mt0, 1));
        mt0 = fmaxf(mt0, __shfl_xor_sync(0xffffffffu, mt0, 2));
        mt1 = fmaxf(mt1, __shfl_xor_sync(0xffffffffu, mt1, 1));
        mt1 = fmaxf(mt1, __shfl_xor_sync(0xffffffffu, mt1, 2));

        const float mn0 = fmaxf(m0, mt0), mn1 = fmaxf(m1, mt1);
        const float al0 = (m0 > -1e37f) ? __expf(m0 - mn0) : 0.f;
        const float al1 = (m1 > -1e37f) ? __expf(m1 - mn1) : 0.f;

        float ps0 = 0.f, ps1 = 0.f;
        #pragma unroll
        for (int j = 0; j < 16; j++) {
            float p0 = (sfr[j][0] > -1e29f) ? __expf(sfr[j][0] - mn0) : 0.f;
            float p1 = (sfr[j][1] > -1e29f) ? __expf(sfr[j][1] - mn0) : 0.f;
            float p2 = (sfr[j][2] > -1e29f) ? __expf(sfr[j][2] - mn1) : 0.f;
            float p3 = (sfr[j][3] > -1e29f) ? __expf(sfr[j][3] - mn1) : 0.f;
            ps0 += p0 + p1; ps1 += p2 + p3;
            sfr[j][0] = tf32r(p0); sfr[j][1] = tf32r(p1);
            sfr[j][2] = tf32r(p2); sfr[j][3] = tf32r(p3);
        }
        ps0 += __shfl_xor_sync(0xffffffffu, ps0, 1);
        ps0 += __shfl_xor_sync(0xffffffffu, ps0, 2);
        ps1 += __shfl_xor_sync(0xffffffffu, ps1, 1);
        ps1 += __shfl_xor_sync(0xffffffffu, ps1, 2);
        l0 = l0 * al0 + ps0;
        l1 = l1 * al1 + ps1;
        m0 = mn0; m1 = mn1;

        #pragma unroll
        for (int j = 0; j < 8; j++) {
            o[j][0] *= al0; o[j][1] *= al0;
            o[j][2] *= al1; o[j][3] *= al1;
        }

        const int srcA = (lane & ~3) | (q4 >> 1);
        const int srcB = srcA + 2;
        const bool odd = (q4 & 1);
        #pragma unroll
        for (int ks = 0; ks < 16; ks++) {
            const float v0a = __shfl_sync(0xffffffffu, sfr[ks][0], srcA);
            const float v1a = __shfl_sync(0xffffffffu, sfr[ks][1], srcA);
            const float v0b = __shfl_sync(0xffffffffu, sfr[ks][0], srcB);
            const float v1b = __shfl_sync(0xffffffffu, sfr[ks][1], srcB);
            const float w0a = __shfl_sync(0xffffffffu, sfr[ks][2], srcA);
            const float w1a = __shfl_sync(0xffffffffu, sfr[ks][3], srcA);
            const float w0b = __shfl_sync(0xffffffffu, sfr[ks][2], srcB);
            const float w1b = __shfl_sync(0xffffffffu, sfr[ks][3], srcB);
            uint32_t a[4];
            a[0] = __float_as_uint(odd ? v1a : v0a);
            a[1] = __float_as_uint(odd ? w1a : w0a);
            a[2] = __float_as_uint(odd ? v1b : v0b);
            a[3] = __float_as_uint(odd ? w1b : w0b);
            const float* vb = Vs + (ks * 8 + q4) * AT_PAD;
            #pragma unroll
            for (int j2 = 0; j2 < 8; j2++) {
                uint32_t bb[2];
                bb[0] = __float_as_uint(vb[j2 * 8 + g]);
                bb[1] = __float_as_uint(vb[4 * AT_PAD + j2 * 8 + g]);
                mma_tf32(o[j2], a, bb);
            }
        }
    }

    const float qm0 = qmask[b * T1_ + i0 + row_g];
    const float qm1 = qmask[b * T1_ + i0 + row_g + 8];
    const float inv0 = (l0 > 0.f) ? qm0 / l0 : 0.f;
    const float inv1 = (l1 > 0.f) ? qm1 / l1 : 0.f;
    __nv_bfloat16* dst0 = AO + ((size_t)(b * T1_ + i0 + row_g)) * INNER_ + h * DH_;
    __nv_bfloat16* dst1 = dst0 + (size_t)8 * INNER_;
    #pragma unroll
    for (int j2 = 0; j2 < 8; j2++) {
        const int cc = j2 * 8 + 2 * q4;
        *reinterpret_cast<__nv_bfloat162*>(dst0 + cc) =
            __floats2bfloat162_rn(o[j2][0] * inv0, o[j2][1] * inv0);
        *reinterpret_cast<__nv_bfloat162*>(dst1 + cc) =
            __floats2bfloat162_rn(o[j2][2] * inv1, o[j2][3] * inv1);
    }
}

// ---------------------------------------------------------------------------
// kernel_launch
// ---------------------------------------------------------------------------
extern "C" void kernel_launch(void* const* d_in, const int* in_sizes, int n_in,
                              void* d_out, int out_size)
{
    const float* qo        = (const float*)d_in[0];
    const float* kvo       = (const float*)d_in[1];
    const void*  amask     = d_in[2];
    const float* qmask     = (const float*)d_in[3];
    const void*  kvmask    = d_in[4];
    const float* ln_g      = (const float*)d_in[5];
    const float* ln_b      = (const float*)d_in[6];
    const float* Wq        = (const float*)d_in[7];
    const float* Wkv       = (const float*)d_in[8];
    const float* Wout      = (const float*)d_in[9];
    const float* attn_gate = (const float*)d_in[10];
    const float* ff_ln_g   = (const float*)d_in[11];
    const float* ff_ln_b   = (const float*)d_in[12];
    const float* W1        = (const float*)d_in[13];
    const float* W2        = (const float*)d_in[14];
    const float* ff_gate   = (const float*)d_in[15];
    float* out = (float*)d_out;

    float *qb, *kvb, *xb;
    __nv_bfloat16 *lnh, *aoh, *hh, *kvoh, *wqt, *wkvt, *woutt, *w1t, *w2t;
    cudaGetSymbolAddress((void**)&qb,    g_q);
    cudaGetSymbolAddress((void**)&kvb,   g_kv);
    cudaGetSymbolAddress((void**)&xb,    g_x);
    cudaGetSymbolAddress((void**)&lnh,   g_ln_h);
    cudaGetSymbolAddress((void**)&aoh,   g_ao_h);
    cudaGetSymbolAddress((void**)&hh,    g_h_h);
    cudaGetSymbolAddress((void**)&kvoh,  g_kvo_h);
    cudaGetSymbolAddress((void**)&wqt,   g_wq_t);
    cudaGetSymbolAddress((void**)&wkvt,  g_wkv_t);
    cudaGetSymbolAddress((void**)&woutt, g_wout_t);
    cudaGetSymbolAddress((void**)&w1t,   g_w1_t);
    cudaGetSymbolAddress((void**)&w2t,   g_w2_t);

    cudaFuncSetAttribute(attn_mma_kernel,
        cudaFuncAttributeMaxDynamicSharedMemorySize, ATTN2_SMEM);

    detect_mask_kernel<<<1, 256>>>((const unsigned int*)amask, 2048);

    const int ROWS = B_ * T1_;   // 8192
    const dim3 tb(32, 8);

    // weight + input conversions (bf16; weights transposed to [N][K])
    f32_to_bf16_kernel<<<(B_ * JT_ * DIM_ / 4 + 255) / 256, 256>>>(
        kvo, kvoh, B_ * JT_ * DIM_ / 4);
    transpose_bf16_kernel<<<dim3(INNER_ / 32, DIM_ / 32), tb>>>(Wq, wqt, DIM_, INNER_);
    transpose_bf16_kernel<<<dim3(2 * INNER_ / 32, DIM_ / 32), tb>>>(Wkv, wkvt, DIM_, 2 * INNER_);
    transpose_bf16_kernel<<<dim3(DIM_ / 32, INNER_ / 32), tb>>>(Wout, woutt, INNER_, DIM_);
    transpose_bf16_kernel<<<dim3(DFF_ / 32, DIM_ / 32), tb>>>(W1, w1t, DIM_, DFF_);
    transpose_bf16_kernel<<<dim3(DIM_ / 32, DFF_ / 32), tb>>>(W2, w2t, DFF_, DIM_);

    // 1) LN(qo) -> bf16
    ln_kernel<<<ROWS, 256>>>(qo, ln_g, ln_b, lnh);
    // 2) q = LN(qo) @ Wq  (f32 out for attention)
    bf16_gemm_kernel<0, 0><<<dim3(INNER_ / 128, ROWS / 128), 256, GEMM_SMEM>>>(
        lnh, wqt, qb, ROWS, INNER_, DIM_, nullptr, nullptr);
    // 3) kv = kvo @ Wkv  (f32 out)
    bf16_gemm_kernel<0, 0><<<dim3(2 * INNER_ / 128, (B_ * JT_) / 128), 256, GEMM_SMEM>>>(
        kvoh, wkvt, kvb, B_ * JT_, 2 * INNER_, DIM_, nullptr, nullptr);
    // 4) attention -> bf16
    attn_mma_kernel<<<dim3(T1_ / 64, H_, B_), 128, ATTN2_SMEM>>>(
        qb, kvb, amask, kvmask, qmask, aoh);
    // 5) x = (ao @ Wout)*tanh(g) + qo  (f32)
    bf16_gemm_kernel<2, 0><<<dim3(DIM_ / 128, ROWS / 128), 256, GEMM_SMEM>>>(
        aoh, woutt, xb, ROWS, DIM_, INNER_, attn_gate, qo);
    // 6) LN(x) -> bf16
    ln_kernel<<<ROWS, 256>>>(xb, ff_ln_g, ff_ln_b, lnh);
    // 7) h = gelu(LN(x) @ W1) -> bf16
    bf16_gemm_kernel<1, 1><<<dim3(DFF_ / 128, ROWS / 128), 256, GEMM_SMEM>>>(
        lnh, w1t, hh, ROWS, DFF_, DIM_, nullptr, nullptr);
    // 8) out = (h @ W2)*tanh(g) + x  (f32)
    bf16_gemm_kernel<2, 0><<<dim3(DIM_ / 128, ROWS / 128), 256, GEMM_SMEM>>>(
        hh, w2t, out, ROWS, DIM_, DFF_, ff_gate, xb);
}

// round 10
// speedup vs baseline: 4.6898x; 1.3325x over previous
#include <cuda_runtime.h>
#include <cuda_bf16.h>
#include <math.h>
#include <stdint.h>

// ---------------------------------------------------------------------------
// Problem constants
// ---------------------------------------------------------------------------
#define B_     4
#define T1_    2048
#define JT_    512
#define DIM_   1024
#define INNER_ 512
#define DFF_   4096
#define H_     8
#define DH_    64

// ---------------------------------------------------------------------------
// Scratch (device globals; no allocation allowed)
// ---------------------------------------------------------------------------
__device__ float g_q [(size_t)B_*T1_*INNER_];
__device__ float g_kv[(size_t)B_*JT_*2*INNER_];
__device__ float g_x [(size_t)B_*T1_*DIM_];
__device__ __nv_bfloat16 g_ln_h [(size_t)B_*T1_*DIM_];
__device__ __nv_bfloat16 g_ao_h [(size_t)B_*T1_*INNER_];
__device__ __nv_bfloat16 g_h_h  [(size_t)B_*T1_*DFF_];
__device__ __nv_bfloat16 g_kvo_h[(size_t)B_*JT_*DIM_];
__device__ __nv_bfloat16 g_wq_t [(size_t)INNER_*DIM_];     // weights, [N][K] bf16
__device__ __nv_bfloat16 g_wkv_t[(size_t)2*INNER_*DIM_];
__device__ __nv_bfloat16 g_wout_t[(size_t)DIM_*INNER_];
__device__ __nv_bfloat16 g_w1_t [(size_t)DFF_*DIM_];
__device__ __nv_bfloat16 g_w2_t [(size_t)DIM_*DFF_];
__device__ unsigned int g_keep[(size_t)B_*T1_*JT_/32];     // packed amask&kvmask bits
__device__ int g_mask_mode;

// ---------------------------------------------------------------------------
// Mask dtype detection (bool may arrive as uint8 / int32 / float32)
// ---------------------------------------------------------------------------
__global__ void detect_mask_kernel(const unsigned int* __restrict__ w, int nwords)
{
    __shared__ int f_u8, f_f32;
    if (threadIdx.x == 0) { f_u8 = 0; f_f32 = 0; }
    __syncthreads();
    int u8 = 0, f32 = 0;
    for (int i = threadIdx.x; i < nwords; i += blockDim.x) {
        unsigned int x = w[i];
        if (x == 0x3F800000u)            f32 = 1;
        else if (x != 0u && x != 1u)     u8  = 1;
    }
    if (u8)  atomicOr(&f_u8, 1);
    if (f32) atomicOr(&f_f32, 1);
    __syncthreads();
    if (threadIdx.x == 0)
        g_mask_mode = f_u8 ? 0 : (f_f32 ? 2 : 1);
}

__device__ __forceinline__ bool read_mask(const void* p, size_t i, int mode)
{
    if (mode == 1) return ((const int*)p)[i] != 0;
    if (mode == 2) return ((const float*)p)[i] != 0.0f;
    return ((const unsigned char*)p)[i] != 0;
}

// ---------------------------------------------------------------------------
// Pack keep bits: bit e of g_keep = amask[e] && kvmask[b, j]. Ballot-packed.
// ---------------------------------------------------------------------------
__global__ __launch_bounds__(256) void pack_keep_kernel(
    const void* __restrict__ amask, const void* __restrict__ kvmask,
    unsigned int* __restrict__ out)
{
    const size_t e = (size_t)blockIdx.x * 256 + threadIdx.x;
    const int mode = g_mask_mode;
    const int b = (int)(e / ((size_t)T1_ * JT_));
    const int j = (int)(e % JT_);
    const bool k = read_mask(amask, e, mode) &&
                   read_mask(kvmask, (size_t)b * JT_ + j, mode);
    const unsigned bal = __ballot_sync(0xffffffffu, k);
    if ((threadIdx.x & 31) == 0) out[e >> 5] = bal;
}

// ---------------------------------------------------------------------------
// Conversion pre-kernels
// ---------------------------------------------------------------------------
__global__ __launch_bounds__(256) void f32_to_bf16_kernel(
    const float* __restrict__ in, __nv_bfloat16* __restrict__ out, int n4)
{
    const int i = blockIdx.x * 256 + threadIdx.x;
    if (i < n4) {
        const float4 v = reinterpret_cast<const float4*>(in)[i];
        __nv_bfloat162* o = reinterpret_cast<__nv_bfloat162*>(out) + i * 2;
        o[0] = __floats2bfloat162_rn(v.x, v.y);
        o[1] = __floats2bfloat162_rn(v.z, v.w);
    }
}

// in: f32 [K][N]  ->  out: bf16 [N][K]
__global__ __launch_bounds__(256) void transpose_bf16_kernel(
    const float* __restrict__ in, __nv_bfloat16* __restrict__ out, int K, int N)
{
    __shared__ float tile[32][33];
    const int n0 = blockIdx.x * 32, k0 = blockIdx.y * 32;
    const int tx = threadIdx.x, ty = threadIdx.y;
    #pragma unroll
    for (int r = ty; r < 32; r += 8)
        tile[r][tx] = in[(size_t)(k0 + r) * N + n0 + tx];
    __syncthreads();
    #pragma unroll
    for (int r = ty; r < 32; r += 8)
        out[(size_t)(n0 + r) * K + k0 + tx] = __float2bfloat16(tile[tx][r]);
}

// ---------------------------------------------------------------------------
// LayerNorm (bf16 out)
// ---------------------------------------------------------------------------
__global__ __launch_bounds__(256) void ln_kernel(
    const float* __restrict__ x, const float* __restrict__ gw,
    const float* __restrict__ bw, __nv_bfloat16* __restrict__ y)
{
    const int row = blockIdx.x;
    const float* xr = x + (size_t)row * DIM_;
    float v[4];
    float s = 0.f, s2 = 0.f;
    #pragma unroll
    for (int k = 0; k < 4; k++) {
        v[k] = xr[threadIdx.x + k * 256];
        s += v[k]; s2 += v[k] * v[k];
    }
    #pragma unroll
    for (int o = 16; o; o >>= 1) {
        s  += __shfl_xor_sync(0xffffffffu, s,  o);
        s2 += __shfl_xor_sync(0xffffffffu, s2, o);
    }
    __shared__ float sh[2][8];
    const int warp = threadIdx.x >> 5, lane = threadIdx.x & 31;
    if (lane == 0) { sh[0][warp] = s; sh[1][warp] = s2; }
    __syncthreads();
    if (threadIdx.x == 0) {
        float S = 0.f, S2 = 0.f;
        #pragma unroll
        for (int w = 0; w < 8; w++) { S += sh[0][w]; S2 += sh[1][w]; }
        const float mu  = S  * (1.0f / DIM_);
        const float var = S2 * (1.0f / DIM_) - mu * mu;
        sh[0][0] = mu;
        sh[1][0] = rsqrtf(var + 1e-5f);
    }
    __syncthreads();
    const float mu = sh[0][0], inv = sh[1][0];
    __nv_bfloat16* yr = y + (size_t)row * DIM_;
    #pragma unroll
    for (int k = 0; k < 4; k++) {
        const int c = threadIdx.x + k * 256;
        yr[c] = __float2bfloat16((v[k] - mu) * inv * gw[c] + bw[c]);
    }
}

// ---------------------------------------------------------------------------
// helpers
// ---------------------------------------------------------------------------
__device__ __forceinline__ float tf32r(float x)
{
    uint32_t r;
    asm("cvt.rna.tf32.f32 %0, %1;" : "=r"(r) : "f"(x));
    return __uint_as_float(r);
}

__device__ __forceinline__ void mma_tf32(
    float* c, const uint32_t* a, const uint32_t* b)
{
    asm volatile(
        "mma.sync.aligned.m16n8k8.row.col.f32.tf32.tf32.f32 "
        "{%0,%1,%2,%3},{%4,%5,%6,%7},{%8,%9},{%0,%1,%2,%3};"
        : "+f"(c[0]), "+f"(c[1]), "+f"(c[2]), "+f"(c[3])
        : "r"(a[0]), "r"(a[1]), "r"(a[2]), "r"(a[3]), "r"(b[0]), "r"(b[1]));
}

__device__ __forceinline__ void mma_bf16(
    float* c, const uint32_t* a, const uint32_t* b)
{
    asm volatile(
        "mma.sync.aligned.m16n8k16.row.col.f32.bf16.bf16.f32 "
        "{%0,%1,%2,%3},{%4,%5,%6,%7},{%8,%9},{%0,%1,%2,%3};"
        : "+f"(c[0]), "+f"(c[1]), "+f"(c[2]), "+f"(c[3])
        : "r"(a[0]), "r"(a[1]), "r"(a[2]), "r"(a[3]), "r"(b[0]), "r"(b[1]));
}

__device__ __forceinline__ void cpa16(void* dst_smem, const void* src_gmem)
{
    uint32_t d = (uint32_t)__cvta_generic_to_shared(dst_smem);
    asm volatile("cp.async.cg.shared.global [%0], [%1], 16;"
                 :: "r"(d), "l"(src_gmem));
}

__device__ __forceinline__ uint32_t smem_u32(const void* p)
{
    uint32_t a;
    asm("{ .reg .u64 t; cvta.to.shared.u64 t, %1; cvt.u32.u64 %0, t; }"
        : "=r"(a) : "l"(p));
    return a;
}

__device__ __forceinline__ void ldsm_x4(
    uint32_t& r0, uint32_t& r1, uint32_t& r2, uint32_t& r3, uint32_t addr)
{
    asm volatile("ldmatrix.sync.aligned.m8n8.x4.shared.b16 {%0,%1,%2,%3}, [%4];"
                 : "=r"(r0), "=r"(r1), "=r"(r2), "=r"(r3) : "r"(addr));
}

// ---------------------------------------------------------------------------
// bf16 tensor-core GEMM: C[M,N] = epi(A[M,K] @ Bt[N,K]^T)
// As R7 (validated numerics) but fragment loads via ldmatrix.x4 (12 per
// K-32 chunk instead of 48 LDS.32). Same pitch-40 smem; LDSM phases are
// bank-conflict-free (banks 20r..20r+3 mod 32 distinct over 8 rows).
// EPI: 0 none, 1 exact GELU, 2 v*tanh(*gate)+res. OBF: bf16 C output.
// ---------------------------------------------------------------------------
#define P_SM 40
#define TILE_B (128 * P_SM)                 // bf16 elems per tile
#define GEMM_SMEM (4 * TILE_B * (int)sizeof(__nv_bfloat16))   // 40960 B

template <int EPI, int OBF>
__global__ __launch_bounds__(256, 2) void bf16_gemm_kernel(
    const __nv_bfloat16* __restrict__ A, const __nv_bfloat16* __restrict__ Bt,
    void* __restrict__ Cv, int M, int N, int K,
    const float* __restrict__ gate, const float* __restrict__ res)
{
    extern __shared__ __nv_bfloat16 smh[];
    __nv_bfloat16* Abuf[2] = { smh,              smh + 2 * TILE_B };
    __nv_bfloat16* Bbuf[2] = { smh + TILE_B,     smh + 3 * TILE_B };
    const uint32_t smb = smem_u32(smh);
    const uint32_t Ab[2] = { smb,                 smb + 4u * TILE_B };  // bytes
    const uint32_t Bb[2] = { smb + 2u * TILE_B,   smb + 6u * TILE_B };

    const int tid  = threadIdx.x;
    const int warp = tid >> 5, lane = tid & 31;
    const int wm = warp >> 1, wn = warp & 1;
    const int g = lane >> 2, q4 = lane & 3;
    const int row0 = blockIdx.y << 7, col0 = blockIdx.x << 7;

    // staging: each thread copies 2 x 16B chunks of one 64B row
    const int sr = tid >> 1;
    const int sc = (tid & 1) << 1;
    const __nv_bfloat16* Ag = A  + (size_t)(row0 + sr) * K + sc * 8;
    const __nv_bfloat16* Bg = Bt + (size_t)(col0 + sr) * K + sc * 8;

    // ldmatrix per-thread address components
    const int a_row0 = wm * 32 + (lane & 15);          // + i*16
    const int a_col0 = (lane >> 4) << 3;               // + ks*16
    const int b_row0 = wn * 64 + ((lane >> 4) << 3) + (lane & 7);  // + jp*16
    const int b_col0 = ((lane >> 3) & 1) << 3;         // + ks*16

    float c[2][8][4];
    #pragma unroll
    for (int i = 0; i < 2; i++)
        #pragma unroll
        for (int j = 0; j < 8; j++)
            #pragma unroll
            for (int q = 0; q < 4; q++) c[i][j][q] = 0.f;

    const int iters = K >> 5;

    cpa16(Abuf[0] + sr * P_SM + sc * 8,     Ag);
    cpa16(Abuf[0] + sr * P_SM + sc * 8 + 8, Ag + 8);
    cpa16(Bbuf[0] + sr * P_SM + sc * 8,     Bg);
    cpa16(Bbuf[0] + sr * P_SM + sc * 8 + 8, Bg + 8);
    asm volatile("cp.async.commit_group;");

    for (int t = 0; t < iters; t++) {
        if (t + 1 < iters) {
            const int k1 = (t + 1) << 5;
            __nv_bfloat16* Ad = Abuf[(t + 1) & 1];
            __nv_bfloat16* Bd = Bbuf[(t + 1) & 1];
            cpa16(Ad + sr * P_SM + sc * 8,     Ag + k1);
            cpa16(Ad + sr * P_SM + sc * 8 + 8, Ag + k1 + 8);
            cpa16(Bd + sr * P_SM + sc * 8,     Bg + k1);
            cpa16(Bd + sr * P_SM + sc * 8 + 8, Bg + k1 + 8);
            asm volatile("cp.async.commit_group;");
            asm volatile("cp.async.wait_group 1;");
        } else {
            asm volatile("cp.async.wait_group 0;");
        }
        __syncthreads();

        const uint32_t sA = Ab[t & 1];
        const uint32_t sB = Bb[t & 1];
        #pragma unroll
        for (int ks = 0; ks < 2; ks++) {
            uint32_t a[2][4], bfr[8][2];
            #pragma unroll
            for (int i = 0; i < 2; i++)
                ldsm_x4(a[i][0], a[i][1], a[i][2], a[i][3],
                        sA + (uint32_t)(((a_row0 + i * 16) * P_SM
                                         + ks * 16 + a_col0) * 2));
            #pragma unroll
            for (int jp = 0; jp < 4; jp++) {
                uint32_t r0, r1, r2, r3;
                ldsm_x4(r0, r1, r2, r3,
                        sB + (uint32_t)(((b_row0 + jp * 16) * P_SM
                                         + ks * 16 + b_col0) * 2));
                bfr[2 * jp][0] = r0; bfr[2 * jp][1] = r1;
                bfr[2 * jp + 1][0] = r2; bfr[2 * jp + 1][1] = r3;
            }
            #pragma unroll
            for (int i = 0; i < 2; i++)
                #pragma unroll
                for (int j = 0; j < 8; j++)
                    mma_bf16(c[i][j], a[i], bfr[j]);
        }
        __syncthreads();
    }

    float gt = 0.f;
    if (EPI == 2) gt = tanhf(gate[0]);
    #pragma unroll
    for (int i = 0; i < 2; i++) {
        const int r_lo = row0 + wm * 32 + i * 16 + g;
        #pragma unroll
        for (int j = 0; j < 8; j++) {
            const int cc = col0 + wn * 64 + j * 8 + 2 * q4;
            #pragma unroll
            for (int half = 0; half < 2; half++) {
                const size_t rr = (size_t)(r_lo + 8 * half);
                float v0 = c[i][j][2 * half + 0];
                float v1 = c[i][j][2 * half + 1];
                if (EPI == 1) {
                    v0 = 0.5f * v0 * (1.0f + erff(v0 * 0.70710678118654752f));
                    v1 = 0.5f * v1 * (1.0f + erff(v1 * 0.70710678118654752f));
                }
                if (EPI == 2) {
                    const float2 rv =
                        *reinterpret_cast<const float2*>(res + rr * N + cc);
                    v0 = v0 * gt + rv.x;
                    v1 = v1 * gt + rv.y;
                }
                if (OBF) {
                    *reinterpret_cast<__nv_bfloat162*>(
                        (__nv_bfloat16*)Cv + rr * N + cc) =
                        __floats2bfloat162_rn(v0, v1);
                } else {
                    *reinterpret_cast<float2*>((float*)Cv + rr * N + cc) =
                        make_float2(v0, v1);
                }
            }
        }
    }
}

// ---------------------------------------------------------------------------
// mma-based fused masked flash attention, v3: 128 query rows per CTA
// (256 threads = 8 warps x 16 rows), packed keep-bitmask from g_keep.
// Per-warp math identical to the validated R4/R7 kernel.
// ---------------------------------------------------------------------------
#define AT_PAD  68
#define ATQ     (128 * AT_PAD)
#define ATTN3_SMEM (3 * ATQ * 4 + 128 * 4 * 4)

__global__ __launch_bounds__(256) void attn_mma_kernel(
    const float* __restrict__ Q,
    const float* __restrict__ KV,
    const unsigned int* __restrict__ KB,   // packed keep bits, 16 words/row
    const float* __restrict__ qmask,
    __nv_bfloat16* __restrict__ AO)
{
    extern __shared__ float sm[];
    float* Qs = sm;                        // 128 x 68
    float* Ks = Qs + ATQ;                  // 128 x 68
    float* Vs = Ks + ATQ;                  // 128 x 68
    unsigned int* keepw = (unsigned int*)(Vs + ATQ);   // 128 x 4 words

    const int i0 = blockIdx.x * 128;
    const int h  = blockIdx.y;
    const int b  = blockIdx.z;
    const int tid  = threadIdx.x;
    const int warp = tid >> 5, lane = tid & 31;
    const int g = lane >> 2, q4 = lane & 3;
    const int row_g = warp * 16 + g;       // rows row_g, row_g+8 (0..127)

    for (int t = tid; t < 128 * 16; t += 256) {
        const int rr = t >> 4, c4 = (t & 15) << 2;
        const float4 v = *reinterpret_cast<const float4*>(
            Q + ((size_t)(b * T1_ + i0 + rr)) * INNER_ + h * DH_ + c4);
        float* d = Qs + rr * AT_PAD + c4;
        d[0] = v.x * 0.125f; d[1] = v.y * 0.125f;
        d[2] = v.z * 0.125f; d[3] = v.w * 0.125f;
    }

    float m0 = -1e38f, m1 = -1e38f, l0 = 0.f, l1 = 0.f;
    float o[8][4];
    #pragma unroll
    for (int j = 0; j < 8; j++)
        #pragma unroll
        for (int q = 0; q < 4; q++) o[j][q] = 0.f;

    for (int kt = 0; kt < 4; kt++) {
        __syncthreads();

        for (int t = tid; t < 128 * 16; t += 256) {
            const int rr = t >> 4, c4 = (t & 15) << 2;
            const float* kp = KV + ((size_t)(b * JT_ + kt * 128 + rr)) * (2 * INNER_)
                                 + h * DH_ + c4;
            const float4 k4 = *reinterpret_cast<const float4*>(kp);
            const float4 v4 = *reinterpret_cast<const float4*>(kp + INNER_);
            float* kd = Ks + rr * AT_PAD + c4;
            kd[0] = tf32r(k4.x); kd[1] = tf32r(k4.y);
            kd[2] = tf32r(k4.z); kd[3] = tf32r(k4.w);
            float* vd = Vs + rr * AT_PAD + c4;
            vd[0] = tf32r(v4.x); vd[1] = tf32r(v4.y);
            vd[2] = tf32r(v4.z); vd[3] = tf32r(v4.w);
        }
        for (int t = tid; t < 128 * 4; t += 256) {
            const int r = t >> 2, w = t & 3;
            keepw[t] = KB[((size_t)(b * T1_ + i0 + r)) * 16 + kt * 4 + w];
        }
        __syncthreads();

        uint32_t kw0[4], kw1[4];
        #pragma unroll
        for (int w = 0; w < 4; w++) {
            kw0[w] = keepw[row_g * 4 + w];
            kw1[w] = keepw[(row_g + 8) * 4 + w];
        }

        uint32_t qa[8][4];
        #pragma unroll
        for (int ks = 0; ks < 8; ks++) {
            const float* base = Qs + (warp * 16) * AT_PAD + ks * 8 + q4;
            qa[ks][0] = __float_as_uint(tf32r(base[g * AT_PAD]));
            qa[ks][1] = __float_as_uint(tf32r(base[(g + 8) * AT_PAD]));
            qa[ks][2] = __float_as_uint(tf32r(base[g * AT_PAD + 4]));
            qa[ks][3] = __float_as_uint(tf32r(base[(g + 8) * AT_PAD + 4]));
        }

        float sfr[16][4];
        #pragma unroll
        for (int j = 0; j < 16; j++)
            #pragma unroll
            for (int q = 0; q < 4; q++) sfr[j][q] = 0.f;
        #pragma unroll
        for (int ks = 0; ks < 8; ks++) {
            #pragma unroll
            for (int j = 0; j < 16; j++) {
                uint32_t bb[2];
                const float* kp = Ks + (j * 8 + g) * AT_PAD + ks * 8 + q4;
                bb[0] = __float_as_uint(kp[0]);
                bb[1] = __float_as_uint(kp[4]);
                mma_tf32(sfr[j], qa[ks], bb);
            }
        }

        float mt0 = -1e30f, mt1 = -1e30f;
        #pragma unroll
        for (int j = 0; j < 16; j++) {
            const int cbit = j * 8 + 2 * q4;
            const uint32_t w0 = kw0[j >> 2] >> (cbit & 31);
            const uint32_t w1 = kw1[j >> 2] >> (cbit & 31);
            sfr[j][0] = (w0 & 1u) ? sfr[j][0] : -1e30f;
            sfr[j][1] = (w0 & 2u) ? sfr[j][1] : -1e30f;
            sfr[j][2] = (w1 & 1u) ? sfr[j][2] : -1e30f;
            sfr[j][3] = (w1 & 2u) ? sfr[j][3] : -1e30f;
            mt0 = fmaxf(mt0, fmaxf(sfr[j][0], sfr[j][1]));
            mt1 = fmaxf(mt1, fmaxf(sfr[j][2], sfr[j][3]));
        }
        mt0 = fmaxf(mt0, __shfl_xor_sync(0xffffffffu, mt0, 1));
        mt0 = fmaxf(mt0, __shfl_xor_sync(0xffffffffu, mt0, 2));
        mt1 = fmaxf(mt1, __shfl_xor_sync(0xffffffffu, mt1, 1));
        mt1 = fmaxf(mt1, __shfl_xor_sync(0xffffffffu, mt1, 2));

        const float mn0 = fmaxf(m0, mt0), mn1 = fmaxf(m1, mt1);
        const float al0 = (m0 > -1e37f) ? __expf(m0 - mn0) : 0.f;
        const float al1 = (m1 > -1e37f) ? __expf(m1 - mn1) : 0.f;

        float ps0 = 0.f, ps1 = 0.f;
        #pragma unroll
        for (int j = 0; j < 16; j++) {
            float p0 = (sfr[j][0] > -1e29f) ? __expf(sfr[j][0] - mn0) : 0.f;
            float p1 = (sfr[j][1] > -1e29f) ? __expf(sfr[j][1] - mn0) : 0.f;
            float p2 = (sfr[j][2] > -1e29f) ? __expf(sfr[j][2] - mn1) : 0.f;
            float p3 = (sfr[j][3] > -1e29f) ? __expf(sfr[j][3] - mn1) : 0.f;
            ps0 += p0 + p1; ps1 += p2 + p3;
            sfr[j][0] = tf32r(p0); sfr[j][1] = tf32r(p1);
            sfr[j][2] = tf32r(p2); sfr[j][3] = tf32r(p3);
        }
        ps0 += __shfl_xor_sync(0xffffffffu, ps0, 1);
        ps0 += __shfl_xor_sync(0xffffffffu, ps0, 2);
        ps1 += __shfl_xor_sync(0xffffffffu, ps1, 1);
        ps1 += __shfl_xor_sync(0xffffffffu, ps1, 2);
        l0 = l0 * al0 + ps0;
        l1 = l1 * al1 + ps1;
        m0 = mn0; m1 = mn1;

        #pragma unroll
        for (int j = 0; j < 8; j++) {
            o[j][0] *= al0; o[j][1] *= al0;
            o[j][2] *= al1; o[j][3] *= al1;
        }

        const int srcA = (lane & ~3) | (q4 >> 1);
        const int srcB = srcA + 2;
        const bool odd = (q4 & 1);
        #pragma unroll
        for (int ks = 0; ks < 16; ks++) {
            const float v0a = __shfl_sync(0xffffffffu, sfr[ks][0], srcA);
            const float v1a = __shfl_sync(0xffffffffu, sfr[ks][1], srcA);
            const float v0b = __shfl_sync(0xffffffffu, sfr[ks][0], srcB);
            const float v1b = __shfl_sync(0xffffffffu, sfr[ks][1], srcB);
            const float w0a = __shfl_sync(0xffffffffu, sfr[ks][2], srcA);
            const float w1a = __shfl_sync(0xffffffffu, sfr[ks][3], srcA);
            const float w0b = __shfl_sync(0xffffffffu, sfr[ks][2], srcB);
            const float w1b = __shfl_sync(0xffffffffu, sfr[ks][3], srcB);
            uint32_t a[4];
            a[0] = __float_as_uint(odd ? v1a : v0a);
            a[1] = __float_as_uint(odd ? w1a : w0a);
            a[2] = __float_as_uint(odd ? v1b : v0b);
            a[3] = __float_as_uint(odd ? w1b : w0b);
            const float* vb = Vs + (ks * 8 + q4) * AT_PAD;
            #pragma unroll
            for (int j2 = 0; j2 < 8; j2++) {
                uint32_t bb[2];
                bb[0] = __float_as_uint(vb[j2 * 8 + g]);
                bb[1] = __float_as_uint(vb[4 * AT_PAD + j2 * 8 + g]);
                mma_tf32(o[j2], a, bb);
            }
        }
    }

    const float qm0 = qmask[b * T1_ + i0 + row_g];
    const float qm1 = qmask[b * T1_ + i0 + row_g + 8];
    const float inv0 = (l0 > 0.f) ? qm0 / l0 : 0.f;
    const float inv1 = (l1 > 0.f) ? qm1 / l1 : 0.f;
    __nv_bfloat16* dst0 = AO + ((size_t)(b * T1_ + i0 + row_g)) * INNER_ + h * DH_;
    __nv_bfloat16* dst1 = dst0 + (size_t)8 * INNER_;
    #pragma unroll
    for (int j2 = 0; j2 < 8; j2++) {
        const int cc = j2 * 8 + 2 * q4;
        *reinterpret_cast<__nv_bfloat162*>(dst0 + cc) =
            __floats2bfloat162_rn(o[j2][0] * inv0, o[j2][1] * inv0);
        *reinterpret_cast<__nv_bfloat162*>(dst1 + cc) =
            __floats2bfloat162_rn(o[j2][2] * inv1, o[j2][3] * inv1);
    }
}

// ---------------------------------------------------------------------------
// kernel_launch
// ---------------------------------------------------------------------------
extern "C" void kernel_launch(void* const* d_in, const int* in_sizes, int n_in,
                              void* d_out, int out_size)
{
    const float* qo        = (const float*)d_in[0];
    const float* kvo       = (const float*)d_in[1];
    const void*  amask     = d_in[2];
    const float* qmask     = (const float*)d_in[3];
    const void*  kvmask    = d_in[4];
    const float* ln_g      = (const float*)d_in[5];
    const float* ln_b      = (const float*)d_in[6];
    const float* Wq        = (const float*)d_in[7];
    const float* Wkv       = (const float*)d_in[8];
    const float* Wout      = (const float*)d_in[9];
    const float* attn_gate = (const float*)d_in[10];
    const float* ff_ln_g   = (const float*)d_in[11];
    const float* ff_ln_b   = (const float*)d_in[12];
    const float* W1        = (const float*)d_in[13];
    const float* W2        = (const float*)d_in[14];
    const float* ff_gate   = (const float*)d_in[15];
    float* out = (float*)d_out;

    float *qb, *kvb, *xb;
    unsigned int* kb;
    __nv_bfloat16 *lnh, *aoh, *hh, *kvoh, *wqt, *wkvt, *woutt, *w1t, *w2t;
    cudaGetSymbolAddress((void**)&qb,    g_q);
    cudaGetSymbolAddress((void**)&kvb,   g_kv);
    cudaGetSymbolAddress((void**)&xb,    g_x);
    cudaGetSymbolAddress((void**)&kb,    g_keep);
    cudaGetSymbolAddress((void**)&lnh,   g_ln_h);
    cudaGetSymbolAddress((void**)&aoh,   g_ao_h);
    cudaGetSymbolAddress((void**)&hh,    g_h_h);
    cudaGetSymbolAddress((void**)&kvoh,  g_kvo_h);
    cudaGetSymbolAddress((void**)&wqt,   g_wq_t);
    cudaGetSymbolAddress((void**)&wkvt,  g_wkv_t);
    cudaGetSymbolAddress((void**)&woutt, g_wout_t);
    cudaGetSymbolAddress((void**)&w1t,   g_w1_t);
    cudaGetSymbolAddress((void**)&w2t,   g_w2_t);

    cudaFuncSetAttribute(attn_mma_kernel,
        cudaFuncAttributeMaxDynamicSharedMemorySize, ATTN3_SMEM);

    detect_mask_kernel<<<1, 256>>>((const unsigned int*)amask, 2048);
    pack_keep_kernel<<<(B_ * T1_ * JT_) / 256, 256>>>(amask, kvmask, kb);

    const int ROWS = B_ * T1_;   // 8192
    const dim3 tb(32, 8);

    // conversions: inputs + weights (weights transposed to [N][K] bf16)
    f32_to_bf16_kernel<<<(B_ * JT_ * DIM_ / 4 + 255) / 256, 256>>>(
        kvo, kvoh, B_ * JT_ * DIM_ / 4);
    transpose_bf16_kernel<<<dim3(INNER_ / 32, DIM_ / 32), tb>>>(Wq, wqt, DIM_, INNER_);
    transpose_bf16_kernel<<<dim3(2 * INNER_ / 32, DIM_ / 32), tb>>>(Wkv, wkvt, DIM_, 2 * INNER_);
    transpose_bf16_kernel<<<dim3(DIM_ / 32, INNER_ / 32), tb>>>(Wout, woutt, INNER_, DIM_);
    transpose_bf16_kernel<<<dim3(DFF_ / 32, DIM_ / 32), tb>>>(W1, w1t, DIM_, DFF_);
    transpose_bf16_kernel<<<dim3(DIM_ / 32, DFF_ / 32), tb>>>(W2, w2t, DFF_, DIM_);

    // 1) LN(qo) -> bf16
    ln_kernel<<<ROWS, 256>>>(qo, ln_g, ln_b, lnh);
    // 2) q = LN(qo) @ Wq  (f32 out for attention)
    bf16_gemm_kernel<0, 0><<<dim3(INNER_ / 128, ROWS / 128), 256, GEMM_SMEM>>>(
        lnh, wqt, qb, ROWS, INNER_, DIM_, nullptr, nullptr);
    // 3) kv = kvo @ Wkv  (f32 out)
    bf16_gemm_kernel<0, 0><<<dim3(2 * INNER_ / 128, (B_ * JT_) / 128), 256, GEMM_SMEM>>>(
        kvoh, wkvt, kvb, B_ * JT_, 2 * INNER_, DIM_, nullptr, nullptr);
    // 4) attention -> bf16
    attn_mma_kernel<<<dim3(T1_ / 128, H_, B_), 256, ATTN3_SMEM>>>(
        qb, kvb, kb, qmask, aoh);
    // 5) x = (ao @ Wout)*tanh(g) + qo  (f32)
    bf16_gemm_kernel<2, 0><<<dim3(DIM_ / 128, ROWS / 128), 256, GEMM_SMEM>>>(
        aoh, woutt, xb, ROWS, DIM_, INNER_, attn_gate, qo);
    // 6) LN(x) -> bf16
    ln_kernel<<<ROWS, 256>>>(xb, ff_ln_g, ff_ln_b, lnh);
    // 7) h = gelu(LN(x) @ W1) -> bf16
    bf16_gemm_kernel<1, 1><<<dim3(DFF_ / 128, ROWS / 128), 256, GEMM_SMEM>>>(
        lnh, w1t, hh, ROWS, DFF_, DIM_, nullptr, nullptr);
    // 8) out = (h @ W2)*tanh(g) + x  (f32)
    bf16_gemm_kernel<2, 0><<<dim3(DIM_ / 128, ROWS / 128), 256, GEMM_SMEM>>>(
        hh, w2t, out, ROWS, DIM_, DFF_, ff_gate, xb);
}